// round 2
// baseline (speedup 1.0000x reference)
#include <cuda_runtime.h>
#include <cuda_bf16.h>
#include <math.h>

#define BATCH 32
#define SEQ   64
#define HID   1024
#define EMB   512
#define VOC   32000
#define G3    3072
#define ROWS  2048   // SEQ*BATCH

#define NBLK  148
#define NTHR  256

// ------------------------------ scratch ---------------------------------
__device__ float g_enc_xg[ROWS * G3];
__device__ float g_dec_xg[ROWS * G3];
__device__ float g_enc_outs[ROWS * HID];
__device__ float g_enc_energy[ROWS * HID];
__device__ float g_dec_h[ROWS * HID];
__device__ float g_hbuf[2][BATCH * HID];
__device__ float g_wh[BATCH * HID];
__device__ float g_ctx[BATCH * HID];
__device__ float g_logits[(size_t)ROWS * VOC];
__device__ float g_tok_lp[ROWS];
__device__ int   g_gidx_enc[ROWS];
__device__ int   g_gidx_dec[ROWS];
__device__ unsigned g_bar_arrive = 0;
__device__ volatile unsigned g_bar_phase = 0;

// ------------------------------ helpers ---------------------------------
__device__ __forceinline__ float tanh_approx(float x) {
    float y; asm("tanh.approx.f32 %0, %1;" : "=f"(y) : "f"(x)); return y;
}

__device__ __forceinline__ void grid_sync() {
    __syncthreads();
    if (threadIdx.x == 0) {
        __threadfence();
        unsigned ph = g_bar_phase;
        unsigned a = atomicAdd(&g_bar_arrive, 1u);
        if (a == (unsigned)(NBLK - 1)) {
            g_bar_arrive = 0u;
            __threadfence();
            g_bar_phase = ph + 1u;
        } else {
            while (g_bar_phase == ph) { __nanosleep(64); }
        }
    }
    __syncthreads();
}

// --------------------------- gather indices -----------------------------
__global__ void build_gather(const int* __restrict__ s, const int* __restrict__ t) {
    int r = blockIdx.x * blockDim.x + threadIdx.x;
    if (r >= ROWS) return;
    int sp = r >> 5, b = r & 31;
    g_gidx_enc[r] = s[b * SEQ + sp];
    g_gidx_dec[r] = (sp == 0) ? -1 : t[b * SEQ + sp - 1];
}

// ------------------------------- SGEMM ----------------------------------
// C[m][n] = sum_k Arow(m)[k] * W[n*ldw + k] + bias[n]
// which: 0=enc_xg (gather enc), 1=dec_xg (gather dec), 2=enc_energy, 3=logits
__global__ void __launch_bounds__(256) sgemm(
    int which,
    const float* __restrict__ emb,
    const float* __restrict__ W, int ldw,
    const float* __restrict__ bias,
    int N, int K)
{
    __shared__ float As[8][128];
    __shared__ float Bs[8][128];
    int tid = threadIdx.x;
    int tx = tid & 15, ty = tid >> 4;
    int bn = blockIdx.x, bm = blockIdx.y;
    int lm = tid >> 1;
    int lk = (tid & 1) * 4;

    int gm = bm * 128 + lm;
    const float* arow;
    if (which == 0)      { int ix = g_gidx_enc[gm]; arow = emb + (size_t)ix * K; }
    else if (which == 1) { int ix = g_gidx_dec[gm]; arow = (ix < 0) ? (const float*)0 : emb + (size_t)ix * K; }
    else if (which == 2) arow = g_enc_outs + (size_t)gm * K;
    else                 arow = g_dec_h + (size_t)gm * K;
    const float* brow = W + (size_t)(bn * 128 + lm) * ldw;

    float acc[8][8];
#pragma unroll
    for (int i = 0; i < 8; i++)
#pragma unroll
        for (int jj = 0; jj < 8; jj++) acc[i][jj] = 0.f;

    float4 av = arow ? *(const float4*)(arow + lk) : make_float4(0.f, 0.f, 0.f, 0.f);
    float4 bv = *(const float4*)(brow + lk);
    for (int k0 = 0; k0 < K; k0 += 8) {
        As[lk + 0][lm] = av.x; As[lk + 1][lm] = av.y; As[lk + 2][lm] = av.z; As[lk + 3][lm] = av.w;
        Bs[lk + 0][lm] = bv.x; Bs[lk + 1][lm] = bv.y; Bs[lk + 2][lm] = bv.z; Bs[lk + 3][lm] = bv.w;
        __syncthreads();
        if (k0 + 8 < K) {
            av = arow ? *(const float4*)(arow + k0 + 8 + lk) : make_float4(0.f, 0.f, 0.f, 0.f);
            bv = *(const float4*)(brow + k0 + 8 + lk);
        }
#pragma unroll
        for (int k = 0; k < 8; k++) {
            float a[8], b[8];
            *(float4*)&a[0] = *(const float4*)&As[k][ty * 8];
            *(float4*)&a[4] = *(const float4*)&As[k][ty * 8 + 4];
            *(float4*)&b[0] = *(const float4*)&Bs[k][tx * 8];
            *(float4*)&b[4] = *(const float4*)&Bs[k][tx * 8 + 4];
#pragma unroll
            for (int i = 0; i < 8; i++)
#pragma unroll
                for (int jj = 0; jj < 8; jj++) acc[i][jj] += a[i] * b[jj];
        }
        __syncthreads();
    }

    float* C = (which == 0) ? g_enc_xg : (which == 1) ? g_dec_xg :
               (which == 2) ? g_enc_energy : g_logits;
    int cn0 = bn * 128 + tx * 8;
    float bb[8];
#pragma unroll
    for (int jj = 0; jj < 8; jj++) bb[jj] = bias ? __ldg(bias + cn0 + jj) : 0.f;
#pragma unroll
    for (int i = 0; i < 8; i++) {
        size_t off = (size_t)(bm * 128 + ty * 8 + i) * N + cn0;
        float4 o0 = make_float4(acc[i][0] + bb[0], acc[i][1] + bb[1], acc[i][2] + bb[2], acc[i][3] + bb[3]);
        float4 o1 = make_float4(acc[i][4] + bb[4], acc[i][5] + bb[5], acc[i][6] + bb[6], acc[i][7] + bb[7]);
        *(float4*)(C + off)     = o0;
        *(float4*)(C + off + 4) = o1;
    }
}

// ---------------------------- encoder scan ------------------------------
__global__ void __launch_bounds__(NTHR) enc_scan(
    const float* __restrict__ Whh, const float* __restrict__ bhh)
{
    __shared__ float sh[BATCH][260];
    int tid = threadIdx.x;
    int warp = tid >> 5, lane = tid & 31;
    int j = blockIdx.x * 8 + warp;
    bool act = (j < HID);

    for (int i = blockIdx.x * NTHR + tid; i < BATCH * HID; i += NBLK * NTHR)
        g_hbuf[0][i] = 0.f;
    grid_sync();

    const float4 *wr0 = 0, *wz0 = 0, *wn0 = 0;
    float br = 0.f, bz = 0.f, bn_ = 0.f;
    if (act) {
        wr0 = (const float4*)(Whh + (size_t)j * HID);
        wz0 = (const float4*)(Whh + (size_t)(HID + j) * HID);
        wn0 = (const float4*)(Whh + (size_t)(2 * HID + j) * HID);
        br = bhh[j]; bz = bhh[HID + j]; bn_ = bhh[2 * HID + j];
    }

    for (int s = 0; s < SEQ; s++) {
        const float* hbuf = g_hbuf[s & 1];
        float* hout = g_hbuf[(s & 1) ^ 1];
        float hr = 0.f, hz = 0.f, hn = 0.f;
        for (int c = 0; c < 4; c++) {
            int j0 = c * 256;
            for (int f = tid; f < BATCH * 64; f += NTHR) {
                int b = f >> 6, q = f & 63;
                *(float4*)&sh[b][q * 4] = __ldcg((const float4*)(hbuf + b * HID + j0) + q);
            }
            __syncthreads();
            if (act) {
                const float4* shb = (const float4*)&sh[lane][0];
                const float4* wr = wr0 + (j0 >> 2);
                const float4* wz = wz0 + (j0 >> 2);
                const float4* wn = wn0 + (j0 >> 2);
#pragma unroll 16
                for (int q = 0; q < 64; q++) {
                    float4 h4 = shb[q];
                    float4 a = __ldg(wr + q), b4 = __ldg(wz + q), c4 = __ldg(wn + q);
                    hr += h4.x * a.x + h4.y * a.y + h4.z * a.z + h4.w * a.w;
                    hz += h4.x * b4.x + h4.y * b4.y + h4.z * b4.z + h4.w * b4.w;
                    hn += h4.x * c4.x + h4.y * c4.y + h4.z * c4.z + h4.w * c4.w;
                }
            }
            __syncthreads();
        }
        if (act) {
            int row = s * BATCH + lane;
            const float* xg = g_enc_xg + (size_t)row * G3;
            float xr = xg[j], xz = xg[HID + j], xn = xg[2 * HID + j];
            float hprev = __ldcg(hbuf + lane * HID + j);
            float r = 1.f / (1.f + expf(-(xr + hr + br)));
            float z = 1.f / (1.f + expf(-(xz + hz + bz)));
            float n = tanhf(xn + r * (hn + bn_));
            float hnew = (1.f - z) * n + z * hprev;
            hout[lane * HID + j] = hnew;
            g_enc_outs[(size_t)row * HID + j] = hnew;
        }
        grid_sync();
    }
}

// ---------------------------- decoder scan ------------------------------
__global__ void __launch_bounds__(NTHR) dec_scan(
    const float* __restrict__ Whh, const float* __restrict__ Wch,
    const float* __restrict__ bhh,
    const float* __restrict__ attn_W, const float* __restrict__ attn_v)
{
    __shared__ float sh[BATCH][260];
    __shared__ float s_wh[HID];
    __shared__ float s_v[HID];
    __shared__ float s_sc[SEQ];
    int tid = threadIdx.x;
    int warp = tid >> 5, lane = tid & 31;
    int j = blockIdx.x * 8 + warp;
    bool act = (j < HID);

    const float4 *whr0 = 0, *whz0 = 0, *whn0 = 0, *wcr0 = 0, *wcz0 = 0, *wcn0 = 0, *wat0 = 0;
    float br = 0.f, bz = 0.f, bn_ = 0.f;
    if (act) {
        whr0 = (const float4*)(Whh + (size_t)j * HID);
        whz0 = (const float4*)(Whh + (size_t)(HID + j) * HID);
        whn0 = (const float4*)(Whh + (size_t)(2 * HID + j) * HID);
        wcr0 = (const float4*)(Wch + (size_t)j * HID);
        wcz0 = (const float4*)(Wch + (size_t)(HID + j) * HID);
        wcn0 = (const float4*)(Wch + (size_t)(2 * HID + j) * HID);
        wat0 = (const float4*)(attn_W + (size_t)j * (2 * HID));  // W_h row j
        br = bhh[j]; bz = bhh[HID + j]; bn_ = bhh[2 * HID + j];
    }

    for (int s = 0; s < SEQ; s++) {
        const float* hbuf = g_hbuf[s & 1];
        float* hout = g_hbuf[(s & 1) ^ 1];

        // ---- phase a: wh[b][j] = h[b] . W_h[j]
        {
            float acc = 0.f;
            for (int c = 0; c < 4; c++) {
                int j0 = c * 256;
                for (int f = tid; f < BATCH * 64; f += NTHR) {
                    int b = f >> 6, q = f & 63;
                    *(float4*)&sh[b][q * 4] = __ldcg((const float4*)(hbuf + b * HID + j0) + q);
                }
                __syncthreads();
                if (act) {
                    const float4* shb = (const float4*)&sh[lane][0];
                    const float4* w = wat0 + (j0 >> 2);
#pragma unroll 16
                    for (int q = 0; q < 64; q++) {
                        float4 h4 = shb[q];
                        float4 a = __ldg(w + q);
                        acc += h4.x * a.x + h4.y * a.y + h4.z * a.z + h4.w * a.w;
                    }
                }
                __syncthreads();
            }
            if (act) g_wh[lane * HID + j] = acc;
        }
        grid_sync();

        // ---- phase bc: scores -> softmax -> ctx  (one block per batch b)
        if (blockIdx.x < BATCH) {
            int b = blockIdx.x;
            for (int k = tid; k < HID; k += NTHR) {
                s_wh[k] = __ldcg(g_wh + b * HID + k);
                s_v[k] = attn_v[k];
            }
            __syncthreads();
            for (int sp = warp; sp < SEQ; sp += 8) {
                const float* ee = g_enc_energy + (size_t)(sp * BATCH + b) * HID;
                float acc = 0.f;
                for (int k = lane; k < HID; k += 32) {
                    float e = ee[k] + s_wh[k];
                    acc += tanh_approx(e) * s_v[k];
                }
#pragma unroll
                for (int o = 16; o; o >>= 1) acc += __shfl_xor_sync(0xffffffffu, acc, o);
                if (lane == 0) s_sc[sp] = acc;
            }
            __syncthreads();
            if (warp == 0) {
                float v0 = s_sc[lane], v1 = s_sc[lane + 32];
                float m = fmaxf(v0, v1);
#pragma unroll
                for (int o = 16; o; o >>= 1) m = fmaxf(m, __shfl_xor_sync(0xffffffffu, m, o));
                float e0 = expf(v0 - m), e1 = expf(v1 - m);
                float ssum = e0 + e1;
#pragma unroll
                for (int o = 16; o; o >>= 1) ssum += __shfl_xor_sync(0xffffffffu, ssum, o);
                float inv = 1.f / ssum;
                s_sc[lane] = e0 * inv; s_sc[lane + 32] = e1 * inv;
            }
            __syncthreads();
            for (int jj = tid; jj < HID; jj += NTHR) {
                float acc = 0.f;
#pragma unroll 8
                for (int sp = 0; sp < SEQ; sp++)
                    acc += s_sc[sp] * g_enc_outs[(size_t)(sp * BATCH + b) * HID + jj];
                g_ctx[b * HID + jj] = acc;
            }
        }
        grid_sync();

        // ---- phase d: gates
        float cr = 0.f, cz = 0.f, cn = 0.f, hr = 0.f, hz = 0.f, hn = 0.f;
        for (int c = 0; c < 4; c++) {        // pass over ctx
            int j0 = c * 256;
            for (int f = tid; f < BATCH * 64; f += NTHR) {
                int b = f >> 6, q = f & 63;
                *(float4*)&sh[b][q * 4] = __ldcg((const float4*)(g_ctx + b * HID + j0) + q);
            }
            __syncthreads();
            if (act) {
                const float4* shb = (const float4*)&sh[lane][0];
                const float4* w1 = wcr0 + (j0 >> 2);
                const float4* w2 = wcz0 + (j0 >> 2);
                const float4* w3 = wcn0 + (j0 >> 2);
#pragma unroll 16
                for (int q = 0; q < 64; q++) {
                    float4 h4 = shb[q];
                    float4 a = __ldg(w1 + q), b4 = __ldg(w2 + q), c4 = __ldg(w3 + q);
                    cr += h4.x * a.x + h4.y * a.y + h4.z * a.z + h4.w * a.w;
                    cz += h4.x * b4.x + h4.y * b4.y + h4.z * b4.z + h4.w * b4.w;
                    cn += h4.x * c4.x + h4.y * c4.y + h4.z * c4.z + h4.w * c4.w;
                }
            }
            __syncthreads();
        }
        for (int c = 0; c < 4; c++) {        // pass over h
            int j0 = c * 256;
            for (int f = tid; f < BATCH * 64; f += NTHR) {
                int b = f >> 6, q = f & 63;
                *(float4*)&sh[b][q * 4] = __ldcg((const float4*)(hbuf + b * HID + j0) + q);
            }
            __syncthreads();
            if (act) {
                const float4* shb = (const float4*)&sh[lane][0];
                const float4* w1 = whr0 + (j0 >> 2);
                const float4* w2 = whz0 + (j0 >> 2);
                const float4* w3 = whn0 + (j0 >> 2);
#pragma unroll 16
                for (int q = 0; q < 64; q++) {
                    float4 h4 = shb[q];
                    float4 a = __ldg(w1 + q), b4 = __ldg(w2 + q), c4 = __ldg(w3 + q);
                    hr += h4.x * a.x + h4.y * a.y + h4.z * a.z + h4.w * a.w;
                    hz += h4.x * b4.x + h4.y * b4.y + h4.z * b4.z + h4.w * b4.w;
                    hn += h4.x * c4.x + h4.y * c4.y + h4.z * c4.z + h4.w * c4.w;
                }
            }
            __syncthreads();
        }
        if (act) {
            int row = s * BATCH + lane;
            const float* xg = g_dec_xg + (size_t)row * G3;
            float xr = xg[j] + cr, xz = xg[HID + j] + cz, xn = xg[2 * HID + j] + cn;
            float hprev = __ldcg(hbuf + lane * HID + j);
            float r = 1.f / (1.f + expf(-(xr + hr + br)));
            float z = 1.f / (1.f + expf(-(xz + hz + bz)));
            float n = tanhf(xn + r * (hn + bn_));
            float hnew = (1.f - z) * n + z * hprev;
            hout[lane * HID + j] = hnew;
            g_dec_h[(size_t)row * HID + j] = hnew;
        }
        grid_sync();
    }
}

// ------------------------------- loss ------------------------------------
__global__ void __launch_bounds__(256) loss_rows(const int* __restrict__ t,
                                                 const int* __restrict__ tlen)
{
    __shared__ float red[256];
    int row = blockIdx.x;
    int sp = row >> 5, b = row & 31;
    const float* lr = g_logits + (size_t)row * VOC;
    int tid = threadIdx.x;
    float m = -3.4e38f;
    for (int i = tid; i < VOC; i += 256) m = fmaxf(m, lr[i]);
    red[tid] = m; __syncthreads();
    for (int o = 128; o; o >>= 1) { if (tid < o) red[tid] = fmaxf(red[tid], red[tid + o]); __syncthreads(); }
    m = red[0]; __syncthreads();
    float ssum = 0.f;
    for (int i = tid; i < VOC; i += 256) ssum += expf(lr[i] - m);
    red[tid] = ssum; __syncthreads();
    for (int o = 128; o; o >>= 1) { if (tid < o) red[tid] += red[tid + o]; __syncthreads(); }
    if (tid == 0) {
        int tgt = t[b * SEQ + sp];
        float lp = lr[tgt] - m - logf(red[0]);
        g_tok_lp[row] = (sp < tlen[b]) ? lp : 0.f;
    }
}

__global__ void __launch_bounds__(256) loss_final(const int* __restrict__ tlen,
                                                  float* __restrict__ out)
{
    __shared__ float red[256];
    int tid = threadIdx.x;
    float ssum = 0.f;
    for (int r = tid; r < ROWS; r += 256) ssum += g_tok_lp[r];
    red[tid] = ssum; __syncthreads();
    for (int o = 128; o; o >>= 1) { if (tid < o) red[tid] += red[tid + o]; __syncthreads(); }
    if (tid == 0) {
        float cnt = 0.f;
        for (int b = 0; b < BATCH; b++) cnt += (float)tlen[b];
        out[0] = -red[0] / cnt;
    }
}

// ------------------------------- launch ----------------------------------
extern "C" void kernel_launch(void* const* d_in, const int* in_sizes, int n_in,
                              void* d_out, int out_size)
{
    const int* s        = (const int*)d_in[0];
    const int* t        = (const int*)d_in[1];
    const int* tlen     = (const int*)d_in[2];
    const float* emb    = (const float*)d_in[3];
    const float* enc_Wih = (const float*)d_in[4];
    const float* enc_Whh = (const float*)d_in[5];
    const float* enc_bih = (const float*)d_in[6];
    const float* enc_bhh = (const float*)d_in[7];
    const float* dec_Wih = (const float*)d_in[8];
    const float* dec_Whh = (const float*)d_in[9];
    const float* dec_Wch = (const float*)d_in[10];
    const float* dec_bih = (const float*)d_in[11];
    const float* dec_bhh = (const float*)d_in[12];
    const float* attn_W  = (const float*)d_in[13];
    const float* attn_v  = (const float*)d_in[14];
    const float* Wout    = (const float*)d_in[15];
    const float* bout    = (const float*)d_in[16];
    float* out = (float*)d_out;

    build_gather<<<8, 256>>>(s, t);
    sgemm<<<dim3(G3 / 128, ROWS / 128), 256>>>(0, emb, enc_Wih, EMB, enc_bih, G3, EMB);
    sgemm<<<dim3(G3 / 128, ROWS / 128), 256>>>(1, emb, dec_Wih, EMB, dec_bih, G3, EMB);
    enc_scan<<<NBLK, NTHR>>>(enc_Whh, enc_bhh);
    sgemm<<<dim3(HID / 128, ROWS / 128), 256>>>(2, emb, attn_W + HID, 2 * HID, (const float*)0, HID, HID);
    dec_scan<<<NBLK, NTHR>>>(dec_Whh, dec_Wch, dec_bhh, attn_W, attn_v);
    sgemm<<<dim3(VOC / 128, ROWS / 128), 256>>>(3, emb, Wout, HID, bout, VOC, HID);
    loss_rows<<<ROWS, 256>>>(t, tlen);
    loss_final<<<1, 256>>>(tlen, out);
}

// round 5
// speedup vs baseline: 1.3175x; 1.3175x over previous
#include <cuda_runtime.h>
#include <cuda_bf16.h>
#include <cstdint>
#include <cstddef>
#include <math.h>

#define BATCH 32
#define SEQ   64
#define HID   1024
#define EMB   512
#define VOC   32000
#define G3    3072
#define ROWS  2048   // SEQ*BATCH

#define NBLK  148
#define NTHR  256

// ------------------------------ scratch ---------------------------------
__device__ float g_enc_xg[ROWS * G3];
__device__ float g_dec_xg[ROWS * G3];
__device__ float g_enc_outs[ROWS * HID];
__device__ float g_enc_energy[ROWS * HID];
__device__ float g_hbuf[2][BATCH * HID];
__device__ float g_wh[BATCH * HID];
__device__ float g_ctx[BATCH * HID];
__device__ float g_logits[(size_t)ROWS * VOC];
__device__ float g_tok_lp[ROWS];
__device__ int   g_gidx_enc[ROWS];
__device__ int   g_gidx_dec[ROWS];
__device__ unsigned g_bar_arrive = 0;
__device__ volatile unsigned g_bar_phase = 0;

// bf16 operands for tensor-core GEMMs
__device__ __align__(16) __nv_bfloat16 g_emb_bf[VOC * EMB];
__device__ __align__(16) __nv_bfloat16 g_encWih_bf[G3 * EMB];
__device__ __align__(16) __nv_bfloat16 g_decWih_bf[G3 * EMB];
__device__ __align__(16) __nv_bfloat16 g_We_bf[HID * HID];
__device__ __align__(16) __nv_bfloat16 g_Wout_bf[(size_t)VOC * HID];
__device__ __align__(16) __nv_bfloat16 g_encouts_bf[ROWS * HID];
__device__ __align__(16) __nv_bfloat16 g_dech_bf[ROWS * HID];

// ------------------------------ helpers ---------------------------------
__device__ __forceinline__ float tanh_approx(float x) {
    float y; asm("tanh.approx.f32 %0, %1;" : "=f"(y) : "f"(x)); return y;
}

__device__ __forceinline__ void grid_sync() {
    __syncthreads();
    if (threadIdx.x == 0) {
        __threadfence();
        unsigned ph = g_bar_phase;
        unsigned a = atomicAdd(&g_bar_arrive, 1u);
        if (a == (unsigned)(NBLK - 1)) {
            g_bar_arrive = 0u;
            __threadfence();
            g_bar_phase = ph + 1u;
        } else {
            while (g_bar_phase == ph) { __nanosleep(32); }
        }
    }
    __syncthreads();
}

__device__ __forceinline__ unsigned int smem_u32(const void* p) {
    return (unsigned int)__cvta_generic_to_shared(p);
}
__device__ __forceinline__ void cp16(unsigned int dst, const void* src, bool pred) {
    int sz = pred ? 16 : 0;
    asm volatile("cp.async.cg.shared.global [%0], [%1], 16, %2;\n"
                 :: "r"(dst), "l"(src), "r"(sz));
}
__device__ __forceinline__ void cp_commit() { asm volatile("cp.async.commit_group;\n"); }
__device__ __forceinline__ void cp_wait0()  { asm volatile("cp.async.wait_group 0;\n"); }
__device__ __forceinline__ void ldsm_x4(unsigned int& r0, unsigned int& r1,
                                        unsigned int& r2, unsigned int& r3, unsigned int a) {
    asm volatile("ldmatrix.sync.aligned.m8n8.x4.shared.b16 {%0,%1,%2,%3},[%4];"
                 : "=r"(r0), "=r"(r1), "=r"(r2), "=r"(r3) : "r"(a));
}
__device__ __forceinline__ void ldsm_x2(unsigned int& r0, unsigned int& r1, unsigned int a) {
    asm volatile("ldmatrix.sync.aligned.m8n8.x2.shared.b16 {%0,%1},[%2];"
                 : "=r"(r0), "=r"(r1) : "r"(a));
}
__device__ __forceinline__ void mma16816(float* c, unsigned int a0, unsigned int a1,
                                         unsigned int a2, unsigned int a3,
                                         unsigned int b0, unsigned int b1) {
    asm volatile("mma.sync.aligned.m16n8k16.row.col.f32.bf16.bf16.f32 "
                 "{%0,%1,%2,%3},{%4,%5,%6,%7},{%8,%9},{%0,%1,%2,%3};"
                 : "+f"(c[0]), "+f"(c[1]), "+f"(c[2]), "+f"(c[3])
                 : "r"(a0), "r"(a1), "r"(a2), "r"(a3), "r"(b0), "r"(b1));
}

// --------------------------- gather indices -----------------------------
__global__ void build_gather(const int* __restrict__ s, const int* __restrict__ t) {
    int r = blockIdx.x * blockDim.x + threadIdx.x;
    if (r >= ROWS) return;
    int sp = r >> 5, b = r & 31;
    g_gidx_enc[r] = s[b * SEQ + sp];
    g_gidx_dec[r] = (sp == 0) ? -1 : t[b * SEQ + sp - 1];
}

// ---------------------------- fp32 -> bf16 -------------------------------
// which: 0=emb, 1=enc_Wih, 2=dec_Wih, 3=Wout
__global__ void f2bf(const float* __restrict__ src, int n, int which) {
    __nv_bfloat16* d;
    if (which == 0) d = g_emb_bf;
    else if (which == 1) d = g_encWih_bf;
    else if (which == 2) d = g_decWih_bf;
    else d = g_Wout_bf;
    int i = (blockIdx.x * blockDim.x + threadIdx.x) * 4;
    if (i < n) {
        float4 v = *(const float4*)(src + i);
        __nv_bfloat16 o[4];
        o[0] = __float2bfloat16(v.x);
        o[1] = __float2bfloat16(v.y);
        o[2] = __float2bfloat16(v.z);
        o[3] = __float2bfloat16(v.w);
        *(uint2*)(d + i) = *(const uint2*)o;
    }
}

__global__ void conv_We(const float* __restrict__ attn_W) {
    int i = blockIdx.x * blockDim.x + threadIdx.x;
    if (i < HID * HID) {
        int j = i >> 10;
        int k = i & 1023;
        g_We_bf[i] = __float2bfloat16(attn_W[(size_t)j * 2048 + 1024 + k]);
    }
}

// ---------------------------- bf16 HMMA GEMM -----------------------------
// C[m][n] = sum_k A(m)[k] * Wb[n][k] + bias[n]
// which: 0 = enc_xg (A gathered from emb via g_gidx_enc, W=enc_Wih)
//        1 = dec_xg (gather dec, neg -> zero row)
//        2 = enc_energy (A=encouts_bf, W=We_bf)
//        3 = logits (A=dech_bf, W=Wout_bf)
#define PADK 40
__global__ void __launch_bounds__(256) hgemm(int which, const float* __restrict__ bias)
{
    __shared__ __nv_bfloat16 As[2][128][PADK];
    __shared__ __nv_bfloat16 Bs[2][128][PADK];
    const unsigned int STG = 128 * PADK * 2;   // bytes per stage

    const __nv_bfloat16* A;
    const __nv_bfloat16* Wb;
    float* C;
    int N, K, gmode;
    if (which == 0) {
        A = g_emb_bf; Wb = g_encWih_bf; C = g_enc_xg; N = G3; K = EMB; gmode = 1;
    } else if (which == 1) {
        A = g_emb_bf; Wb = g_decWih_bf; C = g_dec_xg; N = G3; K = EMB; gmode = 2;
    } else if (which == 2) {
        A = g_encouts_bf; Wb = g_We_bf; C = g_enc_energy; N = HID; K = HID; gmode = 0;
    } else {
        A = g_dech_bf; Wb = g_Wout_bf; C = g_logits; N = VOC; K = HID; gmode = 0;
    }

    int tid = threadIdx.x;
    int bn = blockIdx.x, bm = blockIdx.y;
    int warp = tid >> 5, lane = tid & 31;
    int wm = warp >> 2, wn = warp & 3;     // warp grid 2x4 -> 64x32 tiles

    int lr = tid >> 2;          // 0..63
    int lc = (tid & 3) * 8;     // half offset within K-tile

    const __nv_bfloat16 *a0, *a1;
    bool p0 = true, p1 = true;
    int gm0 = bm * 128 + lr, gm1 = gm0 + 64;
    if (gmode == 0) {
        a0 = A + (size_t)gm0 * K;
        a1 = A + (size_t)gm1 * K;
    } else {
        const int* gi = (gmode == 1) ? g_gidx_enc : g_gidx_dec;
        int i0 = gi[gm0], i1 = gi[gm1];
        p0 = (i0 >= 0);
        p1 = (i1 >= 0);
        a0 = A + (size_t)(p0 ? i0 : 0) * K;
        a1 = A + (size_t)(p1 ? i1 : 0) * K;
    }
    const __nv_bfloat16* b0p = Wb + (size_t)(bn * 128 + lr) * K;
    const __nv_bfloat16* b1p = Wb + (size_t)(bn * 128 + lr + 64) * K;

    unsigned int sa0 = smem_u32(&As[0][lr][lc]);
    unsigned int sa1 = smem_u32(&As[0][lr + 64][lc]);
    unsigned int sb0 = smem_u32(&Bs[0][lr][lc]);
    unsigned int sb1 = smem_u32(&Bs[0][lr + 64][lc]);

    float acc[4][4][4];
#pragma unroll
    for (int mi = 0; mi < 4; mi++) {
#pragma unroll
        for (int ni = 0; ni < 4; ni++) {
#pragma unroll
            for (int q = 0; q < 4; q++) acc[mi][ni][q] = 0.f;
        }
    }

    int arow = wm * 64 + (lane & 15);
    int acol_off = (lane >> 4) * 8;
    int brow = wn * 32 + (lane & 7);
    int bcol_off = ((lane >> 3) & 1) * 8;

    int KT = K / 32;
    cp16(sa0, a0 + lc, p0);
    cp16(sa1, a1 + lc, p1);
    cp16(sb0, b0p + lc, true);
    cp16(sb1, b1p + lc, true);
    cp_commit();

    int stage = 0;
    for (int kt = 0; kt < KT; kt++) {
        cp_wait0();
        __syncthreads();
        if (kt + 1 < KT) {
            int k = (kt + 1) * 32;
            unsigned int off = (unsigned int)(stage ^ 1) * STG;
            cp16(sa0 + off, a0 + k + lc, p0);
            cp16(sa1 + off, a1 + k + lc, p1);
            cp16(sb0 + off, b0p + k + lc, true);
            cp16(sb1 + off, b1p + k + lc, true);
            cp_commit();
        }
#pragma unroll
        for (int ks = 0; ks < 32; ks += 16) {
            unsigned int af[4][4];
#pragma unroll
            for (int mi = 0; mi < 4; mi++) {
                unsigned int addr = smem_u32(&As[stage][arow + mi * 16][ks + acol_off]);
                ldsm_x4(af[mi][0], af[mi][1], af[mi][2], af[mi][3], addr);
            }
            unsigned int bfr[4][2];
#pragma unroll
            for (int ni = 0; ni < 4; ni++) {
                unsigned int addr = smem_u32(&Bs[stage][brow + ni * 8][ks + bcol_off]);
                ldsm_x2(bfr[ni][0], bfr[ni][1], addr);
            }
#pragma unroll
            for (int mi = 0; mi < 4; mi++) {
#pragma unroll
                for (int ni = 0; ni < 4; ni++) {
                    mma16816(acc[mi][ni], af[mi][0], af[mi][1], af[mi][2], af[mi][3],
                             bfr[ni][0], bfr[ni][1]);
                }
            }
        }
        stage ^= 1;
    }

    int row_base = bm * 128 + wm * 64;
    int col_base = bn * 128 + wn * 32;
#pragma unroll
    for (int mi = 0; mi < 4; mi++) {
#pragma unroll
        for (int ni = 0; ni < 4; ni++) {
            int r0 = row_base + mi * 16 + (lane >> 2);
            int c0 = col_base + ni * 8 + (lane & 3) * 2;
            float bv0 = bias ? __ldg(bias + c0) : 0.f;
            float bv1 = bias ? __ldg(bias + c0 + 1) : 0.f;
            float2 v0 = make_float2(acc[mi][ni][0] + bv0, acc[mi][ni][1] + bv1);
            float2 v1 = make_float2(acc[mi][ni][2] + bv0, acc[mi][ni][3] + bv1);
            *(float2*)(C + (size_t)r0 * N + c0) = v0;
            *(float2*)(C + (size_t)(r0 + 8) * N + c0) = v1;
        }
    }
}

// ---------------------------- encoder scan ------------------------------
__global__ void __launch_bounds__(NTHR) enc_scan(
    const float* __restrict__ Whh, const float* __restrict__ bhh)
{
    __shared__ float sh[BATCH][260];
    int tid = threadIdx.x;
    int warp = tid >> 5, lane = tid & 31;
    int j = blockIdx.x * 8 + warp;
    bool act = (j < HID);

    for (int i = blockIdx.x * NTHR + tid; i < BATCH * HID; i += NBLK * NTHR)
        g_hbuf[0][i] = 0.f;
    grid_sync();

    const float4 *wr0 = 0, *wz0 = 0, *wn0 = 0;
    float br = 0.f, bz = 0.f, bn_ = 0.f;
    if (act) {
        wr0 = (const float4*)(Whh + (size_t)j * HID);
        wz0 = (const float4*)(Whh + (size_t)(HID + j) * HID);
        wn0 = (const float4*)(Whh + (size_t)(2 * HID + j) * HID);
        br = bhh[j]; bz = bhh[HID + j]; bn_ = bhh[2 * HID + j];
    }

    for (int s = 0; s < SEQ; s++) {
        const float* hbuf = g_hbuf[s & 1];
        float* hout = g_hbuf[(s & 1) ^ 1];
        float hr = 0.f, hz = 0.f, hn = 0.f;
        for (int c = 0; c < 4; c++) {
            int j0 = c * 256;
            for (int f = tid; f < BATCH * 64; f += NTHR) {
                int b = f >> 6, q = f & 63;
                *(float4*)&sh[b][q * 4] = __ldcg((const float4*)(hbuf + b * HID + j0) + q);
            }
            __syncthreads();
            if (act) {
                const float4* shb = (const float4*)&sh[lane][0];
                const float4* wr = wr0 + (j0 >> 2);
                const float4* wz = wz0 + (j0 >> 2);
                const float4* wn = wn0 + (j0 >> 2);
#pragma unroll 16
                for (int q = 0; q < 64; q++) {
                    float4 h4 = shb[q];
                    float4 a = __ldg(wr + q), b4 = __ldg(wz + q), c4 = __ldg(wn + q);
                    hr += h4.x * a.x + h4.y * a.y + h4.z * a.z + h4.w * a.w;
                    hz += h4.x * b4.x + h4.y * b4.y + h4.z * b4.z + h4.w * b4.w;
                    hn += h4.x * c4.x + h4.y * c4.y + h4.z * c4.z + h4.w * c4.w;
                }
            }
            __syncthreads();
        }
        if (act) {
            int row = s * BATCH + lane;
            const float* xg = g_enc_xg + (size_t)row * G3;
            float xr = xg[j], xz = xg[HID + j], xn = xg[2 * HID + j];
            float hprev = __ldcg(hbuf + lane * HID + j);
            float r = 1.f / (1.f + expf(-(xr + hr + br)));
            float z = 1.f / (1.f + expf(-(xz + hz + bz)));
            float n = tanhf(xn + r * (hn + bn_));
            float hnew = (1.f - z) * n + z * hprev;
            hout[lane * HID + j] = hnew;
            g_enc_outs[(size_t)row * HID + j] = hnew;
            g_encouts_bf[(size_t)row * HID + j] = __float2bfloat16(hnew);
        }
        grid_sync();
    }
}

// ---------------------------- decoder scan ------------------------------
__global__ void __launch_bounds__(NTHR) dec_scan(
    const float* __restrict__ Whh, const float* __restrict__ Wch,
    const float* __restrict__ bhh,
    const float* __restrict__ attn_W, const float* __restrict__ attn_v)
{
    __shared__ float sh[BATCH][260];
    __shared__ float s_wh[HID];
    __shared__ float s_v[HID];
    __shared__ float s_sc[SEQ];
    int tid = threadIdx.x;
    int warp = tid >> 5, lane = tid & 31;
    int j = blockIdx.x * 8 + warp;
    bool act = (j < HID);

    const float4 *whr0 = 0, *whz0 = 0, *whn0 = 0, *wcr0 = 0, *wcz0 = 0, *wcn0 = 0, *wat0 = 0;
    float br = 0.f, bz = 0.f, bn_ = 0.f;
    if (act) {
        whr0 = (const float4*)(Whh + (size_t)j * HID);
        whz0 = (const float4*)(Whh + (size_t)(HID + j) * HID);
        whn0 = (const float4*)(Whh + (size_t)(2 * HID + j) * HID);
        wcr0 = (const float4*)(Wch + (size_t)j * HID);
        wcz0 = (const float4*)(Wch + (size_t)(HID + j) * HID);
        wcn0 = (const float4*)(Wch + (size_t)(2 * HID + j) * HID);
        wat0 = (const float4*)(attn_W + (size_t)j * (2 * HID));  // W_h row j
        br = bhh[j]; bz = bhh[HID + j]; bn_ = bhh[2 * HID + j];
    }

    for (int s = 0; s < SEQ; s++) {
        const float* hbuf = g_hbuf[s & 1];
        float* hout = g_hbuf[(s & 1) ^ 1];

        // ---- phase a: wh[b][j] = h[b] . W_h[j]
        {
            float acc = 0.f;
            for (int c = 0; c < 4; c++) {
                int j0 = c * 256;
                for (int f = tid; f < BATCH * 64; f += NTHR) {
                    int b = f >> 6, q = f & 63;
                    *(float4*)&sh[b][q * 4] = __ldcg((const float4*)(hbuf + b * HID + j0) + q);
                }
                __syncthreads();
                if (act) {
                    const float4* shb = (const float4*)&sh[lane][0];
                    const float4* w = wat0 + (j0 >> 2);
#pragma unroll 16
                    for (int q = 0; q < 64; q++) {
                        float4 h4 = shb[q];
                        float4 a = __ldg(w + q);
                        acc += h4.x * a.x + h4.y * a.y + h4.z * a.z + h4.w * a.w;
                    }
                }
                __syncthreads();
            }
            if (act) g_wh[lane * HID + j] = acc;
        }
        grid_sync();

        // ---- phase bc: scores -> softmax -> ctx  (one block per batch b)
        if (blockIdx.x < BATCH) {
            int b = blockIdx.x;
            for (int k = tid; k < HID; k += NTHR) {
                s_wh[k] = __ldcg(g_wh + b * HID + k);
                s_v[k] = attn_v[k];
            }
            __syncthreads();
            for (int sp = warp; sp < SEQ; sp += 8) {
                const float* ee = g_enc_energy + (size_t)(sp * BATCH + b) * HID;
                float acc = 0.f;
                for (int k = lane; k < HID; k += 32) {
                    float e = ee[k] + s_wh[k];
                    acc += tanh_approx(e) * s_v[k];
                }
#pragma unroll
                for (int o = 16; o; o >>= 1) acc += __shfl_xor_sync(0xffffffffu, acc, o);
                if (lane == 0) s_sc[sp] = acc;
            }
            __syncthreads();
            if (warp == 0) {
                float v0 = s_sc[lane], v1 = s_sc[lane + 32];
                float m = fmaxf(v0, v1);
#pragma unroll
                for (int o = 16; o; o >>= 1) m = fmaxf(m, __shfl_xor_sync(0xffffffffu, m, o));
                float e0 = expf(v0 - m), e1 = expf(v1 - m);
                float ssum = e0 + e1;
#pragma unroll
                for (int o = 16; o; o >>= 1) ssum += __shfl_xor_sync(0xffffffffu, ssum, o);
                float inv = 1.f / ssum;
                s_sc[lane] = e0 * inv; s_sc[lane + 32] = e1 * inv;
            }
            __syncthreads();
            for (int jj = tid; jj < HID; jj += NTHR) {
                float acc = 0.f;
#pragma unroll 8
                for (int sp = 0; sp < SEQ; sp++)
                    acc += s_sc[sp] * g_enc_outs[(size_t)(sp * BATCH + b) * HID + jj];
                g_ctx[b * HID + jj] = acc;
            }
        }
        grid_sync();

        // ---- phase d: gates
        float cr = 0.f, cz = 0.f, cn = 0.f, hr = 0.f, hz = 0.f, hn = 0.f;
        for (int c = 0; c < 4; c++) {        // pass over ctx
            int j0 = c * 256;
            for (int f = tid; f < BATCH * 64; f += NTHR) {
                int b = f >> 6, q = f & 63;
                *(float4*)&sh[b][q * 4] = __ldcg((const float4*)(g_ctx + b * HID + j0) + q);
            }
            __syncthreads();
            if (act) {
                const float4* shb = (const float4*)&sh[lane][0];
                const float4* w1 = wcr0 + (j0 >> 2);
                const float4* w2 = wcz0 + (j0 >> 2);
                const float4* w3 = wcn0 + (j0 >> 2);
#pragma unroll 16
                for (int q = 0; q < 64; q++) {
                    float4 h4 = shb[q];
                    float4 a = __ldg(w1 + q), b4 = __ldg(w2 + q), c4 = __ldg(w3 + q);
                    cr += h4.x * a.x + h4.y * a.y + h4.z * a.z + h4.w * a.w;
                    cz += h4.x * b4.x + h4.y * b4.y + h4.z * b4.z + h4.w * b4.w;
                    cn += h4.x * c4.x + h4.y * c4.y + h4.z * c4.z + h4.w * c4.w;
                }
            }
            __syncthreads();
        }
        for (int c = 0; c < 4; c++) {        // pass over h
            int j0 = c * 256;
            for (int f = tid; f < BATCH * 64; f += NTHR) {
                int b = f >> 6, q = f & 63;
                *(float4*)&sh[b][q * 4] = __ldcg((const float4*)(hbuf + b * HID + j0) + q);
            }
            __syncthreads();
            if (act) {
                const float4* shb = (const float4*)&sh[lane][0];
                const float4* w1 = whr0 + (j0 >> 2);
                const float4* w2 = whz0 + (j0 >> 2);
                const float4* w3 = whn0 + (j0 >> 2);
#pragma unroll 16
                for (int q = 0; q < 64; q++) {
                    float4 h4 = shb[q];
                    float4 a = __ldg(w1 + q), b4 = __ldg(w2 + q), c4 = __ldg(w3 + q);
                    hr += h4.x * a.x + h4.y * a.y + h4.z * a.z + h4.w * a.w;
                    hz += h4.x * b4.x + h4.y * b4.y + h4.z * b4.z + h4.w * b4.w;
                    hn += h4.x * c4.x + h4.y * c4.y + h4.z * c4.z + h4.w * c4.w;
                }
            }
            __syncthreads();
        }
        if (act) {
            int row = s * BATCH + lane;
            const float* xg = g_dec_xg + (size_t)row * G3;
            float xr = xg[j] + cr, xz = xg[HID + j] + cz, xn = xg[2 * HID + j] + cn;
            float hprev = __ldcg(hbuf + lane * HID + j);
            float r = 1.f / (1.f + expf(-(xr + hr + br)));
            float z = 1.f / (1.f + expf(-(xz + hz + bz)));
            float n = tanhf(xn + r * (hn + bn_));
            float hnew = (1.f - z) * n + z * hprev;
            hout[lane * HID + j] = hnew;
            g_dech_bf[(size_t)row * HID + j] = __float2bfloat16(hnew);
        }
        grid_sync();
    }
}

// ------------------------------- loss ------------------------------------
__global__ void __launch_bounds__(256) loss_rows(const int* __restrict__ t,
                                                 const int* __restrict__ tlen)
{
    __shared__ float red[256];
    int row = blockIdx.x;
    int sp = row >> 5, b = row & 31;
    const float* lr = g_logits + (size_t)row * VOC;
    int tid = threadIdx.x;
    float m = -3.4e38f;
    for (int i = tid; i < VOC; i += 256) m = fmaxf(m, lr[i]);
    red[tid] = m; __syncthreads();
    for (int o = 128; o; o >>= 1) {
        if (tid < o) red[tid] = fmaxf(red[tid], red[tid + o]);
        __syncthreads();
    }
    m = red[0]; __syncthreads();
    float ssum = 0.f;
    for (int i = tid; i < VOC; i += 256) ssum += expf(lr[i] - m);
    red[tid] = ssum; __syncthreads();
    for (int o = 128; o; o >>= 1) {
        if (tid < o) red[tid] += red[tid + o];
        __syncthreads();
    }
    if (tid == 0) {
        int tgt = t[b * SEQ + sp];
        float lp = lr[tgt] - m - logf(red[0]);
        g_tok_lp[row] = (sp < tlen[b]) ? lp : 0.f;
    }
}

__global__ void __launch_bounds__(256) loss_final(const int* __restrict__ tlen,
                                                  float* __restrict__ out)
{
    __shared__ float red[256];
    int tid = threadIdx.x;
    float ssum = 0.f;
    for (int r = tid; r < ROWS; r += 256) ssum += g_tok_lp[r];
    red[tid] = ssum; __syncthreads();
    for (int o = 128; o; o >>= 1) {
        if (tid < o) red[tid] += red[tid + o];
        __syncthreads();
    }
    if (tid == 0) {
        float cnt = 0.f;
        for (int b = 0; b < BATCH; b++) cnt += (float)tlen[b];
        out[0] = -red[0] / cnt;
    }
}

// ------------------------------- launch ----------------------------------
extern "C" void kernel_launch(void* const* d_in, const int* in_sizes, int n_in,
                              void* d_out, int out_size)
{
    const int* s         = (const int*)d_in[0];
    const int* t         = (const int*)d_in[1];
    const int* tlen      = (const int*)d_in[2];
    const float* emb     = (const float*)d_in[3];
    const float* enc_Wih = (const float*)d_in[4];
    const float* enc_Whh = (const float*)d_in[5];
    const float* enc_bih = (const float*)d_in[6];
    const float* enc_bhh = (const float*)d_in[7];
    const float* dec_Wih = (const float*)d_in[8];
    const float* dec_Whh = (const float*)d_in[9];
    const float* dec_Wch = (const float*)d_in[10];
    const float* dec_bih = (const float*)d_in[11];
    const float* dec_bhh = (const float*)d_in[12];
    const float* attn_W  = (const float*)d_in[13];
    const float* attn_v  = (const float*)d_in[14];
    const float* Wout    = (const float*)d_in[15];
    const float* bout    = (const float*)d_in[16];
    float* out = (float*)d_out;

    build_gather<<<8, 256>>>(s, t);
    f2bf<<<(VOC * EMB / 4 + 255) / 256, 256>>>(emb, VOC * EMB, 0);
    f2bf<<<(G3 * EMB / 4 + 255) / 256, 256>>>(enc_Wih, G3 * EMB, 1);
    f2bf<<<(G3 * EMB / 4 + 255) / 256, 256>>>(dec_Wih, G3 * EMB, 2);
    conv_We<<<HID * HID / 256, 256>>>(attn_W);
    f2bf<<<(VOC * HID / 4 + 255) / 256, 256>>>(Wout, VOC * HID, 3);

    hgemm<<<dim3(G3 / 128, ROWS / 128), 256>>>(0, enc_bih);
    hgemm<<<dim3(G3 / 128, ROWS / 128), 256>>>(1, dec_bih);
    enc_scan<<<NBLK, NTHR>>>(enc_Whh, enc_bhh);
    hgemm<<<dim3(HID / 128, ROWS / 128), 256>>>(2, (const float*)0);
    dec_scan<<<NBLK, NTHR>>>(dec_Whh, dec_Wch, dec_bhh, attn_W, attn_v);
    hgemm<<<dim3(VOC / 128, ROWS / 128), 256>>>(3, bout);
    loss_rows<<<ROWS, 256>>>(t, tlen);
    loss_final<<<1, 256>>>(tlen, out);
}

// round 6
// speedup vs baseline: 1.7172x; 1.3034x over previous
#include <cuda_runtime.h>
#include <cuda_bf16.h>
#include <cstdint>
#include <cstddef>
#include <math.h>

#define BATCH 32
#define SEQ   64
#define HID   1024
#define EMB   512
#define VOC   32000
#define G3    3072
#define ROWS  2048   // SEQ*BATCH

#define NBLK  148
#define SNTHR 512    // scan kernels: 16 warps

// ------------------------------ scratch ---------------------------------
__device__ float g_enc_xg[ROWS * G3];
__device__ float g_dec_xg[ROWS * G3];
__device__ float g_enc_outs[ROWS * HID];
__device__ float g_enc_energy[ROWS * HID];
__device__ float g_hbuf[2][BATCH * HID];
__device__ float g_wh[BATCH * HID];
__device__ float g_ctx[BATCH * HID];
__device__ float g_logits[(size_t)ROWS * VOC];
__device__ float g_tok_lp[ROWS];
__device__ int   g_gidx_enc[ROWS];
__device__ int   g_gidx_dec[ROWS];
__device__ unsigned g_bar_arrive = 0;
__device__ volatile unsigned g_bar_phase = 0;

// bf16 operands for tensor-core GEMMs
__device__ __align__(16) __nv_bfloat16 g_emb_bf[VOC * EMB];
__device__ __align__(16) __nv_bfloat16 g_encWih_bf[G3 * EMB];
__device__ __align__(16) __nv_bfloat16 g_decWih_bf[G3 * EMB];
__device__ __align__(16) __nv_bfloat16 g_We_bf[HID * HID];
__device__ __align__(16) __nv_bfloat16 g_Wout_bf[(size_t)VOC * HID];
__device__ __align__(16) __nv_bfloat16 g_encouts_bf[ROWS * HID];
__device__ __align__(16) __nv_bfloat16 g_dech_bf[ROWS * HID];

// ------------------------------ helpers ---------------------------------
__device__ __forceinline__ float tanh_approx(float x) {
    float y; asm("tanh.approx.f32 %0, %1;" : "=f"(y) : "f"(x)); return y;
}

__device__ __forceinline__ void grid_sync() {
    __syncthreads();
    if (threadIdx.x == 0) {
        __threadfence();
        unsigned ph = g_bar_phase;
        unsigned a = atomicAdd(&g_bar_arrive, 1u);
        if (a == (unsigned)(NBLK - 1)) {
            g_bar_arrive = 0u;
            __threadfence();
            g_bar_phase = ph + 1u;
        } else {
            while (g_bar_phase == ph) { __nanosleep(32); }
        }
    }
    __syncthreads();
}

__device__ __forceinline__ unsigned int smem_u32(const void* p) {
    return (unsigned int)__cvta_generic_to_shared(p);
}
__device__ __forceinline__ void cp16(unsigned int dst, const void* src, bool pred) {
    int sz = pred ? 16 : 0;
    asm volatile("cp.async.cg.shared.global [%0], [%1], 16, %2;\n"
                 :: "r"(dst), "l"(src), "r"(sz));
}
__device__ __forceinline__ void cp_commit() { asm volatile("cp.async.commit_group;\n"); }
__device__ __forceinline__ void cp_wait0()  { asm volatile("cp.async.wait_group 0;\n"); }
__device__ __forceinline__ void ldsm_x4(unsigned int& r0, unsigned int& r1,
                                        unsigned int& r2, unsigned int& r3, unsigned int a) {
    asm volatile("ldmatrix.sync.aligned.m8n8.x4.shared.b16 {%0,%1,%2,%3},[%4];"
                 : "=r"(r0), "=r"(r1), "=r"(r2), "=r"(r3) : "r"(a));
}
__device__ __forceinline__ void ldsm_x2(unsigned int& r0, unsigned int& r1, unsigned int a) {
    asm volatile("ldmatrix.sync.aligned.m8n8.x2.shared.b16 {%0,%1},[%2];"
                 : "=r"(r0), "=r"(r1) : "r"(a));
}
__device__ __forceinline__ void mma16816(float* c, unsigned int a0, unsigned int a1,
                                         unsigned int a2, unsigned int a3,
                                         unsigned int b0, unsigned int b1) {
    asm volatile("mma.sync.aligned.m16n8k16.row.col.f32.bf16.bf16.f32 "
                 "{%0,%1,%2,%3},{%4,%5,%6,%7},{%8,%9},{%0,%1,%2,%3};"
                 : "+f"(c[0]), "+f"(c[1]), "+f"(c[2]), "+f"(c[3])
                 : "r"(a0), "r"(a1), "r"(a2), "r"(a3), "r"(b0), "r"(b1));
}

// --------------------------- gather indices -----------------------------
__global__ void build_gather(const int* __restrict__ s, const int* __restrict__ t) {
    int r = blockIdx.x * blockDim.x + threadIdx.x;
    if (r >= ROWS) return;
    int sp = r >> 5, b = r & 31;
    g_gidx_enc[r] = s[b * SEQ + sp];
    g_gidx_dec[r] = (sp == 0) ? -1 : t[b * SEQ + sp - 1];
}

// ---------------------------- fp32 -> bf16 -------------------------------
__global__ void f2bf(const float* __restrict__ src, int n, int which) {
    __nv_bfloat16* d;
    if (which == 0) d = g_emb_bf;
    else if (which == 1) d = g_encWih_bf;
    else if (which == 2) d = g_decWih_bf;
    else d = g_Wout_bf;
    int i = (blockIdx.x * blockDim.x + threadIdx.x) * 4;
    if (i < n) {
        float4 v = *(const float4*)(src + i);
        __nv_bfloat16 o[4];
        o[0] = __float2bfloat16(v.x);
        o[1] = __float2bfloat16(v.y);
        o[2] = __float2bfloat16(v.z);
        o[3] = __float2bfloat16(v.w);
        *(uint2*)(d + i) = *(const uint2*)o;
    }
}

__global__ void conv_We(const float* __restrict__ attn_W) {
    int i = blockIdx.x * blockDim.x + threadIdx.x;
    if (i < HID * HID) {
        int j = i >> 10;
        int k = i & 1023;
        g_We_bf[i] = __float2bfloat16(attn_W[(size_t)j * 2048 + 1024 + k]);
    }
}

// ---------------------------- bf16 HMMA GEMM -----------------------------
#define PADK 40
__global__ void __launch_bounds__(256) hgemm(int which, const float* __restrict__ bias)
{
    __shared__ __nv_bfloat16 As[2][128][PADK];
    __shared__ __nv_bfloat16 Bs[2][128][PADK];
    const unsigned int STG = 128 * PADK * 2;

    const __nv_bfloat16* A;
    const __nv_bfloat16* Wb;
    float* C;
    int N, K, gmode;
    if (which == 0) {
        A = g_emb_bf; Wb = g_encWih_bf; C = g_enc_xg; N = G3; K = EMB; gmode = 1;
    } else if (which == 1) {
        A = g_emb_bf; Wb = g_decWih_bf; C = g_dec_xg; N = G3; K = EMB; gmode = 2;
    } else if (which == 2) {
        A = g_encouts_bf; Wb = g_We_bf; C = g_enc_energy; N = HID; K = HID; gmode = 0;
    } else {
        A = g_dech_bf; Wb = g_Wout_bf; C = g_logits; N = VOC; K = HID; gmode = 0;
    }

    int tid = threadIdx.x;
    int bn = blockIdx.x, bm = blockIdx.y;
    int warp = tid >> 5, lane = tid & 31;
    int wm = warp >> 2, wn = warp & 3;

    int lr = tid >> 2;
    int lc = (tid & 3) * 8;

    const __nv_bfloat16 *a0, *a1;
    bool p0 = true, p1 = true;
    int gm0 = bm * 128 + lr, gm1 = gm0 + 64;
    if (gmode == 0) {
        a0 = A + (size_t)gm0 * K;
        a1 = A + (size_t)gm1 * K;
    } else {
        const int* gi = (gmode == 1) ? g_gidx_enc : g_gidx_dec;
        int i0 = gi[gm0], i1 = gi[gm1];
        p0 = (i0 >= 0);
        p1 = (i1 >= 0);
        a0 = A + (size_t)(p0 ? i0 : 0) * K;
        a1 = A + (size_t)(p1 ? i1 : 0) * K;
    }
    const __nv_bfloat16* b0p = Wb + (size_t)(bn * 128 + lr) * K;
    const __nv_bfloat16* b1p = Wb + (size_t)(bn * 128 + lr + 64) * K;

    unsigned int sa0 = smem_u32(&As[0][lr][lc]);
    unsigned int sa1 = smem_u32(&As[0][lr + 64][lc]);
    unsigned int sb0 = smem_u32(&Bs[0][lr][lc]);
    unsigned int sb1 = smem_u32(&Bs[0][lr + 64][lc]);

    float acc[4][4][4];
#pragma unroll
    for (int mi = 0; mi < 4; mi++) {
#pragma unroll
        for (int ni = 0; ni < 4; ni++) {
#pragma unroll
            for (int q = 0; q < 4; q++) acc[mi][ni][q] = 0.f;
        }
    }

    int arow = wm * 64 + (lane & 15);
    int acol_off = (lane >> 4) * 8;
    int brow = wn * 32 + (lane & 7);
    int bcol_off = ((lane >> 3) & 1) * 8;

    int KT = K / 32;
    cp16(sa0, a0 + lc, p0);
    cp16(sa1, a1 + lc, p1);
    cp16(sb0, b0p + lc, true);
    cp16(sb1, b1p + lc, true);
    cp_commit();

    int stage = 0;
    for (int kt = 0; kt < KT; kt++) {
        cp_wait0();
        __syncthreads();
        if (kt + 1 < KT) {
            int k = (kt + 1) * 32;
            unsigned int off = (unsigned int)(stage ^ 1) * STG;
            cp16(sa0 + off, a0 + k + lc, p0);
            cp16(sa1 + off, a1 + k + lc, p1);
            cp16(sb0 + off, b0p + k + lc, true);
            cp16(sb1 + off, b1p + k + lc, true);
            cp_commit();
        }
#pragma unroll
        for (int ks = 0; ks < 32; ks += 16) {
            unsigned int af[4][4];
#pragma unroll
            for (int mi = 0; mi < 4; mi++) {
                unsigned int addr = smem_u32(&As[stage][arow + mi * 16][ks + acol_off]);
                ldsm_x4(af[mi][0], af[mi][1], af[mi][2], af[mi][3], addr);
            }
            unsigned int bfr[4][2];
#pragma unroll
            for (int ni = 0; ni < 4; ni++) {
                unsigned int addr = smem_u32(&Bs[stage][brow + ni * 8][ks + bcol_off]);
                ldsm_x2(bfr[ni][0], bfr[ni][1], addr);
            }
#pragma unroll
            for (int mi = 0; mi < 4; mi++) {
#pragma unroll
                for (int ni = 0; ni < 4; ni++) {
                    mma16816(acc[mi][ni], af[mi][0], af[mi][1], af[mi][2], af[mi][3],
                             bfr[ni][0], bfr[ni][1]);
                }
            }
        }
        stage ^= 1;
    }

    int row_base = bm * 128 + wm * 64;
    int col_base = bn * 128 + wn * 32;
#pragma unroll
    for (int mi = 0; mi < 4; mi++) {
#pragma unroll
        for (int ni = 0; ni < 4; ni++) {
            int r0 = row_base + mi * 16 + (lane >> 2);
            int c0 = col_base + ni * 8 + (lane & 3) * 2;
            float bv0 = bias ? __ldg(bias + c0) : 0.f;
            float bv1 = bias ? __ldg(bias + c0 + 1) : 0.f;
            float2 v0 = make_float2(acc[mi][ni][0] + bv0, acc[mi][ni][1] + bv1);
            float2 v1 = make_float2(acc[mi][ni][2] + bv0, acc[mi][ni][3] + bv1);
            *(float2*)(C + (size_t)r0 * N + c0) = v0;
            *(float2*)(C + (size_t)(r0 + 8) * N + c0) = v1;
        }
    }
}

// ---------------------------- encoder scan ------------------------------
// 512 threads: warp = (jw 0..7, kh 0..1). Each (j, khalf) warp does a 512-long
// dot per gate with 4 independent accumulator chains; khalf partials combined
// in smem. Staging buffer sh[kh][b][132]: per-b stride 132 floats (mod32=4)
// -> conflict-free LDS.128.
__global__ void __launch_bounds__(SNTHR) enc_scan(
    const float* __restrict__ Whh, const float* __restrict__ bhh)
{
    __shared__ float sh[2][BATCH][132];
    __shared__ float part[8][3][32];
    int tid = threadIdx.x;
    int warp = tid >> 5, lane = tid & 31;
    int jw = warp & 7, kh = warp >> 3;
    int j = blockIdx.x * 8 + jw;
    bool act = (j < HID);

    for (int i = blockIdx.x * SNTHR + tid; i < BATCH * HID; i += NBLK * SNTHR)
        g_hbuf[0][i] = 0.f;
    grid_sync();

    const float4 *wr0 = 0, *wz0 = 0, *wn0 = 0;
    float br = 0.f, bz = 0.f, bn_ = 0.f;
    if (act) {
        wr0 = (const float4*)(Whh + (size_t)j * HID + kh * 512);
        wz0 = (const float4*)(Whh + (size_t)(HID + j) * HID + kh * 512);
        wn0 = (const float4*)(Whh + (size_t)(2 * HID + j) * HID + kh * 512);
        br = bhh[j]; bz = bhh[HID + j]; bn_ = bhh[2 * HID + j];
    }

    for (int s = 0; s < SEQ; s++) {
        const float* hbuf = g_hbuf[s & 1];
        float* hout = g_hbuf[(s & 1) ^ 1];
        float4 ar = make_float4(0.f, 0.f, 0.f, 0.f);
        float4 az = ar, an = ar;
        for (int it = 0; it < 4; it++) {
            // stage chunk `it` of both k-halves (2*32*128 floats)
            for (int f = tid; f < 2048; f += SNTHR) {
                int half = f >> 10, rem = f & 1023;
                int b = rem >> 5, q = rem & 31;
                *(float4*)&sh[half][b][q * 4] =
                    __ldcg((const float4*)(hbuf + b * HID + half * 512 + it * 128) + q);
            }
            __syncthreads();
            if (act) {
                const float4* shb = (const float4*)&sh[kh][lane][0];
                const float4* wr = wr0 + it * 32;
                const float4* wz = wz0 + it * 32;
                const float4* wn = wn0 + it * 32;
#pragma unroll 8
                for (int q = 0; q < 32; q++) {
                    float4 h4 = shb[q];
                    float4 a = __ldg(wr + q), b4 = __ldg(wz + q), c4 = __ldg(wn + q);
                    ar.x += h4.x * a.x;  ar.y += h4.y * a.y;  ar.z += h4.z * a.z;  ar.w += h4.w * a.w;
                    az.x += h4.x * b4.x; az.y += h4.y * b4.y; az.z += h4.z * b4.z; az.w += h4.w * b4.w;
                    an.x += h4.x * c4.x; an.y += h4.y * c4.y; an.z += h4.z * c4.z; an.w += h4.w * c4.w;
                }
            }
            __syncthreads();
        }
        float hr = (ar.x + ar.y) + (ar.z + ar.w);
        float hz = (az.x + az.y) + (az.z + az.w);
        float hn = (an.x + an.y) + (an.z + an.w);
        if (act && kh == 1) {
            part[jw][0][lane] = hr;
            part[jw][1][lane] = hz;
            part[jw][2][lane] = hn;
        }
        __syncthreads();
        if (act && kh == 0) {
            hr += part[jw][0][lane];
            hz += part[jw][1][lane];
            hn += part[jw][2][lane];
            int row = s * BATCH + lane;
            const float* xg = g_enc_xg + (size_t)row * G3;
            float xr = xg[j], xz = xg[HID + j], xn = xg[2 * HID + j];
            float hprev = __ldcg(hbuf + lane * HID + j);
            float r = 1.f / (1.f + expf(-(xr + hr + br)));
            float z = 1.f / (1.f + expf(-(xz + hz + bz)));
            float n = tanhf(xn + r * (hn + bn_));
            float hnew = (1.f - z) * n + z * hprev;
            hout[lane * HID + j] = hnew;
            g_enc_outs[(size_t)row * HID + j] = hnew;
            g_encouts_bf[(size_t)row * HID + j] = __float2bfloat16(hnew);
        }
        grid_sync();
    }
}

// ---------------------------- decoder scan ------------------------------
__global__ void __launch_bounds__(SNTHR) dec_scan(
    const float* __restrict__ Whh, const float* __restrict__ Wch,
    const float* __restrict__ bhh,
    const float* __restrict__ attn_W, const float* __restrict__ attn_v)
{
    __shared__ float sh[2][BATCH][132];
    __shared__ float part[8][6][32];
    __shared__ float partw[8][32];
    __shared__ float s_wh[HID];
    __shared__ float s_sc[SEQ];
    int tid = threadIdx.x;
    int warp = tid >> 5, lane = tid & 31;
    int jw = warp & 7, kh = warp >> 3;
    int j = blockIdx.x * 8 + jw;
    bool act = (j < HID);

    const float4 *whr0 = 0, *whz0 = 0, *whn0 = 0;
    const float4 *wcr0 = 0, *wcz0 = 0, *wcn0 = 0, *wat0 = 0;
    float br = 0.f, bz = 0.f, bn_ = 0.f;
    if (act) {
        whr0 = (const float4*)(Whh + (size_t)j * HID + kh * 512);
        whz0 = (const float4*)(Whh + (size_t)(HID + j) * HID + kh * 512);
        whn0 = (const float4*)(Whh + (size_t)(2 * HID + j) * HID + kh * 512);
        wcr0 = (const float4*)(Wch + (size_t)j * HID + kh * 512);
        wcz0 = (const float4*)(Wch + (size_t)(HID + j) * HID + kh * 512);
        wcn0 = (const float4*)(Wch + (size_t)(2 * HID + j) * HID + kh * 512);
        wat0 = (const float4*)(attn_W + (size_t)j * (2 * HID) + kh * 512);
        br = bhh[j]; bz = bhh[HID + j]; bn_ = bhh[2 * HID + j];
    }

    for (int s = 0; s < SEQ; s++) {
        const float* hbuf = g_hbuf[s & 1];
        float* hout = g_hbuf[(s & 1) ^ 1];

        // ---- phase a: wh[b][j] = h[b] . W_h[j]
        {
            float4 aw = make_float4(0.f, 0.f, 0.f, 0.f);
            for (int it = 0; it < 4; it++) {
                for (int f = tid; f < 2048; f += SNTHR) {
                    int half = f >> 10, rem = f & 1023;
                    int b = rem >> 5, q = rem & 31;
                    *(float4*)&sh[half][b][q * 4] =
                        __ldcg((const float4*)(hbuf + b * HID + half * 512 + it * 128) + q);
                }
                __syncthreads();
                if (act) {
                    const float4* shb = (const float4*)&sh[kh][lane][0];
                    const float4* w = wat0 + it * 32;
#pragma unroll 8
                    for (int q = 0; q < 32; q++) {
                        float4 h4 = shb[q];
                        float4 a = __ldg(w + q);
                        aw.x += h4.x * a.x; aw.y += h4.y * a.y;
                        aw.z += h4.z * a.z; aw.w += h4.w * a.w;
                    }
                }
                __syncthreads();
            }
            float acc = (aw.x + aw.y) + (aw.z + aw.w);
            if (act && kh == 1) partw[jw][lane] = acc;
            __syncthreads();
            if (act && kh == 0) g_wh[lane * HID + j] = acc + partw[jw][lane];
        }
        grid_sync();

        // ---- phase bc: scores -> softmax -> ctx  (one block per batch b)
        if (blockIdx.x < BATCH) {
            int b = blockIdx.x;
            for (int k = tid; k < HID; k += SNTHR)
                s_wh[k] = __ldcg(g_wh + b * HID + k);
            __syncthreads();
            for (int sp = warp; sp < SEQ; sp += 16) {
                const float* ee = g_enc_energy + (size_t)(sp * BATCH + b) * HID;
                float acc = 0.f;
                for (int k = lane; k < HID; k += 32) {
                    float e = ee[k] + s_wh[k];
                    acc += tanh_approx(e) * __ldg(attn_v + k);
                }
#pragma unroll
                for (int o = 16; o; o >>= 1) acc += __shfl_xor_sync(0xffffffffu, acc, o);
                if (lane == 0) s_sc[sp] = acc;
            }
            __syncthreads();
            if (warp == 0) {
                float v0 = s_sc[lane], v1 = s_sc[lane + 32];
                float m = fmaxf(v0, v1);
#pragma unroll
                for (int o = 16; o; o >>= 1) m = fmaxf(m, __shfl_xor_sync(0xffffffffu, m, o));
                float e0 = expf(v0 - m), e1 = expf(v1 - m);
                float ssum = e0 + e1;
#pragma unroll
                for (int o = 16; o; o >>= 1) ssum += __shfl_xor_sync(0xffffffffu, ssum, o);
                float inv = 1.f / ssum;
                s_sc[lane] = e0 * inv; s_sc[lane + 32] = e1 * inv;
            }
            __syncthreads();
            for (int jj = tid; jj < HID; jj += SNTHR) {
                float a0 = 0.f, a1 = 0.f, a2 = 0.f, a3 = 0.f;
#pragma unroll 4
                for (int sp = 0; sp < SEQ; sp += 4) {
                    a0 += s_sc[sp]     * g_enc_outs[(size_t)((sp)     * BATCH + b) * HID + jj];
                    a1 += s_sc[sp + 1] * g_enc_outs[(size_t)((sp + 1) * BATCH + b) * HID + jj];
                    a2 += s_sc[sp + 2] * g_enc_outs[(size_t)((sp + 2) * BATCH + b) * HID + jj];
                    a3 += s_sc[sp + 3] * g_enc_outs[(size_t)((sp + 3) * BATCH + b) * HID + jj];
                }
                g_ctx[b * HID + jj] = (a0 + a1) + (a2 + a3);
            }
        }
        grid_sync();

        // ---- phase d: gates (ctx pass then h pass)
        float4 acr = make_float4(0.f, 0.f, 0.f, 0.f);
        float4 acz = acr, acn = acr, ahr = acr, ahz = acr, ahn = acr;
        for (int it = 0; it < 4; it++) {       // ctx pass
            for (int f = tid; f < 2048; f += SNTHR) {
                int half = f >> 10, rem = f & 1023;
                int b = rem >> 5, q = rem & 31;
                *(float4*)&sh[half][b][q * 4] =
                    __ldcg((const float4*)(g_ctx + b * HID + half * 512 + it * 128) + q);
            }
            __syncthreads();
            if (act) {
                const float4* shb = (const float4*)&sh[kh][lane][0];
                const float4* w1 = wcr0 + it * 32;
                const float4* w2 = wcz0 + it * 32;
                const float4* w3 = wcn0 + it * 32;
#pragma unroll 8
                for (int q = 0; q < 32; q++) {
                    float4 h4 = shb[q];
                    float4 a = __ldg(w1 + q), b4 = __ldg(w2 + q), c4 = __ldg(w3 + q);
                    acr.x += h4.x * a.x;  acr.y += h4.y * a.y;  acr.z += h4.z * a.z;  acr.w += h4.w * a.w;
                    acz.x += h4.x * b4.x; acz.y += h4.y * b4.y; acz.z += h4.z * b4.z; acz.w += h4.w * b4.w;
                    acn.x += h4.x * c4.x; acn.y += h4.y * c4.y; acn.z += h4.z * c4.z; acn.w += h4.w * c4.w;
                }
            }
            __syncthreads();
        }
        for (int it = 0; it < 4; it++) {       // h pass
            for (int f = tid; f < 2048; f += SNTHR) {
                int half = f >> 10, rem = f & 1023;
                int b = rem >> 5, q = rem & 31;
                *(float4*)&sh[half][b][q * 4] =
                    __ldcg((const float4*)(hbuf + b * HID + half * 512 + it * 128) + q);
            }
            __syncthreads();
            if (act) {
                const float4* shb = (const float4*)&sh[kh][lane][0];
                const float4* w1 = whr0 + it * 32;
                const float4* w2 = whz0 + it * 32;
                const float4* w3 = whn0 + it * 32;
#pragma unroll 8
                for (int q = 0; q < 32; q++) {
                    float4 h4 = shb[q];
                    float4 a = __ldg(w1 + q), b4 = __ldg(w2 + q), c4 = __ldg(w3 + q);
                    ahr.x += h4.x * a.x;  ahr.y += h4.y * a.y;  ahr.z += h4.z * a.z;  ahr.w += h4.w * a.w;
                    ahz.x += h4.x * b4.x; ahz.y += h4.y * b4.y; ahz.z += h4.z * b4.z; ahz.w += h4.w * b4.w;
                    ahn.x += h4.x * c4.x; ahn.y += h4.y * c4.y; ahn.z += h4.z * c4.z; ahn.w += h4.w * c4.w;
                }
            }
            __syncthreads();
        }
        float cr = (acr.x + acr.y) + (acr.z + acr.w);
        float cz = (acz.x + acz.y) + (acz.z + acz.w);
        float cn = (acn.x + acn.y) + (acn.z + acn.w);
        float hr = (ahr.x + ahr.y) + (ahr.z + ahr.w);
        float hz = (ahz.x + ahz.y) + (ahz.z + ahz.w);
        float hn = (ahn.x + ahn.y) + (ahn.z + ahn.w);
        if (act && kh == 1) {
            part[jw][0][lane] = cr; part[jw][1][lane] = cz; part[jw][2][lane] = cn;
            part[jw][3][lane] = hr; part[jw][4][lane] = hz; part[jw][5][lane] = hn;
        }
        __syncthreads();
        if (act && kh == 0) {
            cr += part[jw][0][lane]; cz += part[jw][1][lane]; cn += part[jw][2][lane];
            hr += part[jw][3][lane]; hz += part[jw][4][lane]; hn += part[jw][5][lane];
            int row = s * BATCH + lane;
            const float* xg = g_dec_xg + (size_t)row * G3;
            float xr = xg[j] + cr, xz = xg[HID + j] + cz, xn = xg[2 * HID + j] + cn;
            float hprev = __ldcg(hbuf + lane * HID + j);
            float r = 1.f / (1.f + expf(-(xr + hr + br)));
            float z = 1.f / (1.f + expf(-(xz + hz + bz)));
            float n = tanhf(xn + r * (hn + bn_));
            float hnew = (1.f - z) * n + z * hprev;
            hout[lane * HID + j] = hnew;
            g_dech_bf[(size_t)row * HID + j] = __float2bfloat16(hnew);
        }
        grid_sync();
    }
}

// ------------------------------- loss ------------------------------------
__global__ void __launch_bounds__(256) loss_rows(const int* __restrict__ t,
                                                 const int* __restrict__ tlen)
{
    __shared__ float red[256];
    int row = blockIdx.x;
    int sp = row >> 5, b = row & 31;
    const float* lr = g_logits + (size_t)row * VOC;
    int tid = threadIdx.x;
    float m = -3.4e38f;
    for (int i = tid; i < VOC; i += 256) m = fmaxf(m, lr[i]);
    red[tid] = m; __syncthreads();
    for (int o = 128; o; o >>= 1) {
        if (tid < o) red[tid] = fmaxf(red[tid], red[tid + o]);
        __syncthreads();
    }
    m = red[0]; __syncthreads();
    float ssum = 0.f;
    for (int i = tid; i < VOC; i += 256) ssum += expf(lr[i] - m);
    red[tid] = ssum; __syncthreads();
    for (int o = 128; o; o >>= 1) {
        if (tid < o) red[tid] += red[tid + o];
        __syncthreads();
    }
    if (tid == 0) {
        int tgt = t[b * SEQ + sp];
        float lp = lr[tgt] - m - logf(red[0]);
        g_tok_lp[row] = (sp < tlen[b]) ? lp : 0.f;
    }
}

__global__ void __launch_bounds__(256) loss_final(const int* __restrict__ tlen,
                                                  float* __restrict__ out)
{
    __shared__ float red[256];
    int tid = threadIdx.x;
    float ssum = 0.f;
    for (int r = tid; r < ROWS; r += 256) ssum += g_tok_lp[r];
    red[tid] = ssum; __syncthreads();
    for (int o = 128; o; o >>= 1) {
        if (tid < o) red[tid] += red[tid + o];
        __syncthreads();
    }
    if (tid == 0) {
        float cnt = 0.f;
        for (int b = 0; b < BATCH; b++) cnt += (float)tlen[b];
        out[0] = -red[0] / cnt;
    }
}

// ------------------------------- launch ----------------------------------
extern "C" void kernel_launch(void* const* d_in, const int* in_sizes, int n_in,
                              void* d_out, int out_size)
{
    const int* s         = (const int*)d_in[0];
    const int* t         = (const int*)d_in[1];
    const int* tlen      = (const int*)d_in[2];
    const float* emb     = (const float*)d_in[3];
    const float* enc_Wih = (const float*)d_in[4];
    const float* enc_Whh = (const float*)d_in[5];
    const float* enc_bih = (const float*)d_in[6];
    const float* enc_bhh = (const float*)d_in[7];
    const float* dec_Wih = (const float*)d_in[8];
    const float* dec_Whh = (const float*)d_in[9];
    const float* dec_Wch = (const float*)d_in[10];
    const float* dec_bih = (const float*)d_in[11];
    const float* dec_bhh = (const float*)d_in[12];
    const float* attn_W  = (const float*)d_in[13];
    const float* attn_v  = (const float*)d_in[14];
    const float* Wout    = (const float*)d_in[15];
    const float* bout    = (const float*)d_in[16];
    float* out = (float*)d_out;

    build_gather<<<8, 256>>>(s, t);
    f2bf<<<(VOC * EMB / 4 + 255) / 256, 256>>>(emb, VOC * EMB, 0);
    f2bf<<<(G3 * EMB / 4 + 255) / 256, 256>>>(enc_Wih, G3 * EMB, 1);
    f2bf<<<(G3 * EMB / 4 + 255) / 256, 256>>>(dec_Wih, G3 * EMB, 2);
    conv_We<<<HID * HID / 256, 256>>>(attn_W);
    f2bf<<<(VOC * HID / 4 + 255) / 256, 256>>>(Wout, VOC * HID, 3);

    hgemm<<<dim3(G3 / 128, ROWS / 128), 256>>>(0, enc_bih);
    hgemm<<<dim3(G3 / 128, ROWS / 128), 256>>>(1, dec_bih);
    enc_scan<<<NBLK, SNTHR>>>(enc_Whh, enc_bhh);
    hgemm<<<dim3(HID / 128, ROWS / 128), 256>>>(2, (const float*)0);
    dec_scan<<<NBLK, SNTHR>>>(dec_Whh, dec_Wch, dec_bhh, attn_W, attn_v);
    hgemm<<<dim3(VOC / 128, ROWS / 128), 256>>>(3, bout);
    loss_rows<<<ROWS, 256>>>(t, tlen);
    loss_final<<<1, 256>>>(tlen, out);
}

// round 7
// speedup vs baseline: 4.7783x; 2.7826x over previous
#include <cuda_runtime.h>
#include <cuda_bf16.h>
#include <cstdint>
#include <cstddef>
#include <math.h>

#define BATCH 32
#define SEQ   64
#define HID   1024
#define EMB   512
#define VOC   32000
#define G3    3072
#define ROWS  2048   // SEQ*BATCH

#define NBLK  128    // persistent scan blocks (HID/8)
#define SNTHR 512    // 16 warps

// padded smem row stride for bf16 weight/activation tiles: 1024 + 8 elems
#define RSTRIDE 1032           // elements
#define RSTRIDE_B 2064         // bytes

// enc smem carve
#define ENC_W_BYTES   (24 * RSTRIDE_B)                 // 49536
#define ENC_HS_OFF    ENC_W_BYTES
#define ENC_GRED_OFF  (ENC_HS_OFF + 32 * RSTRIDE_B)    // 115584
#define ENC_SM_TOTAL  (ENC_GRED_OFF + 8 * 32 * 24 * 4) // 140160

// dec smem carve
#define DEC_W_BYTES   (56 * RSTRIDE_B)                  // 115584
#define DEC_HS_OFF    DEC_W_BYTES
#define DEC_GRED_OFF  (DEC_HS_OFF + 32 * RSTRIDE_B)     // 181632
#define DEC_WHRED_OFF (DEC_GRED_OFF + 8 * 32 * 24 * 4)  // 206208
#define DEC_SWH_OFF   (DEC_WHRED_OFF + 8 * 32 * 8 * 4)  // 214400
#define DEC_SSC_OFF   (DEC_SWH_OFF + HID * 4)           // 218496
#define DEC_SM_TOTAL  (DEC_SSC_OFF + SEQ * 4)           // 218752

// ------------------------------ scratch ---------------------------------
__device__ float g_enc_xg[ROWS * G3];
__device__ float g_dec_xg[ROWS * G3];
__device__ float g_enc_outs[ROWS * HID];
__device__ float g_enc_energy[ROWS * HID];
__device__ float g_hbuf[2][BATCH * HID];
__device__ float g_wh[BATCH * HID];
__device__ float g_logits[(size_t)ROWS * VOC];
__device__ float g_tok_lp[ROWS];
__device__ int   g_gidx_enc[ROWS];
__device__ int   g_gidx_dec[ROWS];
__device__ unsigned g_bar_arrive = 0;
__device__ volatile unsigned g_bar_phase = 0;

// bf16 operands
__device__ __align__(16) __nv_bfloat16 g_emb_bf[VOC * EMB];
__device__ __align__(16) __nv_bfloat16 g_encWih_bf[G3 * EMB];
__device__ __align__(16) __nv_bfloat16 g_decWih_bf[G3 * EMB];
__device__ __align__(16) __nv_bfloat16 g_We_bf[HID * HID];
__device__ __align__(16) __nv_bfloat16 g_Wh_bf[HID * HID];
__device__ __align__(16) __nv_bfloat16 g_Wout_bf[(size_t)VOC * HID];
__device__ __align__(16) __nv_bfloat16 g_encouts_bf[ROWS * HID];
__device__ __align__(16) __nv_bfloat16 g_dech_bf[ROWS * HID];
__device__ __align__(16) __nv_bfloat16 g_encWhh_bf[G3 * HID];
__device__ __align__(16) __nv_bfloat16 g_decWhh_bf[G3 * HID];
__device__ __align__(16) __nv_bfloat16 g_decWch_bf[G3 * HID];
__device__ __align__(16) __nv_bfloat16 g_hbuf_bf[2][BATCH * HID];
__device__ __align__(16) __nv_bfloat16 g_ctx_bf[BATCH * HID];

// ------------------------------ helpers ---------------------------------
__device__ __forceinline__ float tanh_approx(float x) {
    float y; asm("tanh.approx.f32 %0, %1;" : "=f"(y) : "f"(x)); return y;
}

__device__ __forceinline__ void grid_sync() {
    __syncthreads();
    if (threadIdx.x == 0) {
        __threadfence();
        unsigned ph = g_bar_phase;
        unsigned a = atomicAdd(&g_bar_arrive, 1u);
        if (a == (unsigned)(NBLK - 1)) {
            g_bar_arrive = 0u;
            __threadfence();
            g_bar_phase = ph + 1u;
        } else {
            while (g_bar_phase == ph) { __nanosleep(32); }
        }
    }
    __syncthreads();
}

__device__ __forceinline__ unsigned int smem_u32(const void* p) {
    return (unsigned int)__cvta_generic_to_shared(p);
}
__device__ __forceinline__ void cp16(unsigned int dst, const void* src, bool pred) {
    int sz = pred ? 16 : 0;
    asm volatile("cp.async.cg.shared.global [%0], [%1], 16, %2;\n"
                 :: "r"(dst), "l"(src), "r"(sz));
}
__device__ __forceinline__ void cp_commit() { asm volatile("cp.async.commit_group;\n"); }
__device__ __forceinline__ void cp_wait0()  { asm volatile("cp.async.wait_group 0;\n"); }
__device__ __forceinline__ void ldsm_x4(unsigned int& r0, unsigned int& r1,
                                        unsigned int& r2, unsigned int& r3, unsigned int a) {
    asm volatile("ldmatrix.sync.aligned.m8n8.x4.shared.b16 {%0,%1,%2,%3},[%4];"
                 : "=r"(r0), "=r"(r1), "=r"(r2), "=r"(r3) : "r"(a));
}
__device__ __forceinline__ void ldsm_x2(unsigned int& r0, unsigned int& r1, unsigned int a) {
    asm volatile("ldmatrix.sync.aligned.m8n8.x2.shared.b16 {%0,%1},[%2];"
                 : "=r"(r0), "=r"(r1) : "r"(a));
}
__device__ __forceinline__ void mma16816(float* c, unsigned int a0, unsigned int a1,
                                         unsigned int a2, unsigned int a3,
                                         unsigned int b0, unsigned int b1) {
    asm volatile("mma.sync.aligned.m16n8k16.row.col.f32.bf16.bf16.f32 "
                 "{%0,%1,%2,%3},{%4,%5,%6,%7},{%8,%9},{%0,%1,%2,%3};"
                 : "+f"(c[0]), "+f"(c[1]), "+f"(c[2]), "+f"(c[3])
                 : "r"(a0), "r"(a1), "r"(a2), "r"(a3), "r"(b0), "r"(b1));
}

// --------------------------- gather indices -----------------------------
__global__ void build_gather(const int* __restrict__ s, const int* __restrict__ t) {
    int r = blockIdx.x * blockDim.x + threadIdx.x;
    if (r >= ROWS) return;
    int sp = r >> 5, b = r & 31;
    g_gidx_enc[r] = s[b * SEQ + sp];
    g_gidx_dec[r] = (sp == 0) ? -1 : t[b * SEQ + sp - 1];
}

// ---------------------------- fp32 -> bf16 -------------------------------
// which: 0=emb 1=encWih 2=decWih 3=Wout 4=encWhh 5=decWhh 6=decWch
__global__ void f2bf(const float* __restrict__ src, int n, int which) {
    __nv_bfloat16* d;
    if (which == 0) d = g_emb_bf;
    else if (which == 1) d = g_encWih_bf;
    else if (which == 2) d = g_decWih_bf;
    else if (which == 3) d = g_Wout_bf;
    else if (which == 4) d = g_encWhh_bf;
    else if (which == 5) d = g_decWhh_bf;
    else d = g_decWch_bf;
    int i = (blockIdx.x * blockDim.x + threadIdx.x) * 4;
    if (i < n) {
        float4 v = *(const float4*)(src + i);
        __nv_bfloat16 o[4];
        o[0] = __float2bfloat16(v.x);
        o[1] = __float2bfloat16(v.y);
        o[2] = __float2bfloat16(v.z);
        o[3] = __float2bfloat16(v.w);
        *(uint2*)(d + i) = *(const uint2*)o;
    }
}

__global__ void conv_attnW(const float* __restrict__ attn_W) {
    int i = blockIdx.x * blockDim.x + threadIdx.x;
    if (i < HID * HID) {
        int j = i >> 10;
        int k = i & 1023;
        g_We_bf[i] = __float2bfloat16(attn_W[(size_t)j * 2048 + 1024 + k]);
        g_Wh_bf[i] = __float2bfloat16(attn_W[(size_t)j * 2048 + k]);
    }
}

// ---------------------------- bf16 HMMA GEMM -----------------------------
#define PADK 40
__global__ void __launch_bounds__(256) hgemm(int which, const float* __restrict__ bias)
{
    __shared__ __nv_bfloat16 As[2][128][PADK];
    __shared__ __nv_bfloat16 Bs[2][128][PADK];
    const unsigned int STG = 128 * PADK * 2;

    const __nv_bfloat16* A;
    const __nv_bfloat16* Wb;
    float* C;
    int N, K, gmode;
    if (which == 0) {
        A = g_emb_bf; Wb = g_encWih_bf; C = g_enc_xg; N = G3; K = EMB; gmode = 1;
    } else if (which == 1) {
        A = g_emb_bf; Wb = g_decWih_bf; C = g_dec_xg; N = G3; K = EMB; gmode = 2;
    } else if (which == 2) {
        A = g_encouts_bf; Wb = g_We_bf; C = g_enc_energy; N = HID; K = HID; gmode = 0;
    } else {
        A = g_dech_bf; Wb = g_Wout_bf; C = g_logits; N = VOC; K = HID; gmode = 0;
    }

    int tid = threadIdx.x;
    int bn = blockIdx.x, bm = blockIdx.y;
    int warp = tid >> 5, lane = tid & 31;
    int wm = warp >> 2, wn = warp & 3;

    int lr = tid >> 2;
    int lc = (tid & 3) * 8;

    const __nv_bfloat16 *a0, *a1;
    bool p0 = true, p1 = true;
    int gm0 = bm * 128 + lr, gm1 = gm0 + 64;
    if (gmode == 0) {
        a0 = A + (size_t)gm0 * K;
        a1 = A + (size_t)gm1 * K;
    } else {
        const int* gi = (gmode == 1) ? g_gidx_enc : g_gidx_dec;
        int i0 = gi[gm0], i1 = gi[gm1];
        p0 = (i0 >= 0);
        p1 = (i1 >= 0);
        a0 = A + (size_t)(p0 ? i0 : 0) * K;
        a1 = A + (size_t)(p1 ? i1 : 0) * K;
    }
    const __nv_bfloat16* b0p = Wb + (size_t)(bn * 128 + lr) * K;
    const __nv_bfloat16* b1p = Wb + (size_t)(bn * 128 + lr + 64) * K;

    unsigned int sa0 = smem_u32(&As[0][lr][lc]);
    unsigned int sa1 = smem_u32(&As[0][lr + 64][lc]);
    unsigned int sb0 = smem_u32(&Bs[0][lr][lc]);
    unsigned int sb1 = smem_u32(&Bs[0][lr + 64][lc]);

    float acc[4][4][4];
#pragma unroll
    for (int mi = 0; mi < 4; mi++) {
#pragma unroll
        for (int ni = 0; ni < 4; ni++) {
#pragma unroll
            for (int q = 0; q < 4; q++) acc[mi][ni][q] = 0.f;
        }
    }

    int arow = wm * 64 + (lane & 15);
    int acol_off = (lane >> 4) * 8;
    int brow = wn * 32 + (lane & 7);
    int bcol_off = ((lane >> 3) & 1) * 8;

    int KT = K / 32;
    cp16(sa0, a0 + lc, p0);
    cp16(sa1, a1 + lc, p1);
    cp16(sb0, b0p + lc, true);
    cp16(sb1, b1p + lc, true);
    cp_commit();

    int stage = 0;
    for (int kt = 0; kt < KT; kt++) {
        cp_wait0();
        __syncthreads();
        if (kt + 1 < KT) {
            int k = (kt + 1) * 32;
            unsigned int off = (unsigned int)(stage ^ 1) * STG;
            cp16(sa0 + off, a0 + k + lc, p0);
            cp16(sa1 + off, a1 + k + lc, p1);
            cp16(sb0 + off, b0p + k + lc, true);
            cp16(sb1 + off, b1p + k + lc, true);
            cp_commit();
        }
#pragma unroll
        for (int ks = 0; ks < 32; ks += 16) {
            unsigned int af[4][4];
#pragma unroll
            for (int mi = 0; mi < 4; mi++) {
                unsigned int addr = smem_u32(&As[stage][arow + mi * 16][ks + acol_off]);
                ldsm_x4(af[mi][0], af[mi][1], af[mi][2], af[mi][3], addr);
            }
            unsigned int bfr[4][2];
#pragma unroll
            for (int ni = 0; ni < 4; ni++) {
                unsigned int addr = smem_u32(&Bs[stage][brow + ni * 8][ks + bcol_off]);
                ldsm_x2(bfr[ni][0], bfr[ni][1], addr);
            }
#pragma unroll
            for (int mi = 0; mi < 4; mi++) {
#pragma unroll
                for (int ni = 0; ni < 4; ni++) {
                    mma16816(acc[mi][ni], af[mi][0], af[mi][1], af[mi][2], af[mi][3],
                             bfr[ni][0], bfr[ni][1]);
                }
            }
        }
        stage ^= 1;
    }

    int row_base = bm * 128 + wm * 64;
    int col_base = bn * 128 + wn * 32;
#pragma unroll
    for (int mi = 0; mi < 4; mi++) {
#pragma unroll
        for (int ni = 0; ni < 4; ni++) {
            int r0 = row_base + mi * 16 + (lane >> 2);
            int c0 = col_base + ni * 8 + (lane & 3) * 2;
            float bv0 = bias ? __ldg(bias + c0) : 0.f;
            float bv1 = bias ? __ldg(bias + c0 + 1) : 0.f;
            float2 v0 = make_float2(acc[mi][ni][0] + bv0, acc[mi][ni][1] + bv1);
            float2 v1 = make_float2(acc[mi][ni][2] + bv0, acc[mi][ni][3] + bv1);
            *(float2*)(C + (size_t)r0 * N + c0) = v0;
            *(float2*)(C + (size_t)(r0 + 8) * N + c0) = v1;
        }
    }
}

// ---------------------------- encoder scan (HMMA) ------------------------
// 128 blocks x 512 thr. Block owns j0..j0+7. Weights (24 gate rows, bf16)
// resident in smem. Per step: stage bf16 h (32x1024), warps (mw,kw) do
// m16n8k16 partial MMAs, smem-reduce over kw, fp32 GRU epilogue.
__global__ void __launch_bounds__(SNTHR) enc_scan(const float* __restrict__ bhh)
{
    extern __shared__ char sm[];
    __nv_bfloat16* Wsm = (__nv_bfloat16*)sm;
    __nv_bfloat16* hs  = (__nv_bfloat16*)(sm + ENC_HS_OFF);
    float* Gred        = (float*)(sm + ENC_GRED_OFF);

    int tid = threadIdx.x;
    int w = tid >> 5, lane = tid & 31;
    int mw = w & 1, kw = w >> 1;
    int j0 = blockIdx.x * 8;

    // preload bf16 weight slice: rows 0..7=r, 8..15=z, 16..23=n for j0..j0+7
    for (int f = tid; f < 24 * 128; f += SNTHR) {
        int r = f >> 7, c = f & 127;
        int grow = (r < 8) ? (j0 + r) : (r < 16) ? (1024 + j0 + r - 8) : (2048 + j0 + r - 16);
        cp16(smem_u32(Wsm + r * RSTRIDE + c * 8), g_encWhh_bf + (size_t)grow * HID + c * 8, true);
    }
    cp_commit();
    // zero h0 (fp32 + bf16)
    for (int i = blockIdx.x * SNTHR + tid; i < BATCH * HID; i += NBLK * SNTHR) {
        g_hbuf[0][i] = 0.f;
        g_hbuf_bf[0][i] = __float2bfloat16(0.f);
    }
    cp_wait0();
    __syncthreads();
    grid_sync();

    int jj = tid & 7, b = tid >> 3;   // valid for tid<256
    float br = 0.f, bz = 0.f, bn_ = 0.f;
    if (tid < 256) {
        br = bhh[j0 + jj]; bz = bhh[1024 + j0 + jj]; bn_ = bhh[2048 + j0 + jj];
    }

    unsigned int aBase = smem_u32(hs) + (unsigned)((mw * 16 + (lane & 15)) * RSTRIDE_B + ((lane >> 4) * 8) * 2);
    unsigned int bBase = smem_u32(Wsm) + (unsigned)((lane & 7) * RSTRIDE_B + (((lane >> 3) & 1) * 8) * 2);

    for (int s = 0; s < SEQ; s++) {
        int hb = s & 1;
        // stage bf16 h
        for (int f = tid; f < 32 * 128; f += SNTHR) {
            int r = f >> 7, c = f & 127;
            cp16(smem_u32(hs + r * RSTRIDE + c * 8), g_hbuf_bf[hb] + r * HID + c * 8, true);
        }
        cp_commit(); cp_wait0(); __syncthreads();

        float cG[3][4];
#pragma unroll
        for (int nt = 0; nt < 3; nt++) {
#pragma unroll
            for (int q = 0; q < 4; q++) cG[nt][q] = 0.f;
        }
#pragma unroll
        for (int kt = 0; kt < 8; kt++) {
            int k16 = kw * 8 + kt;
            unsigned int a0, a1, a2, a3;
            ldsm_x4(a0, a1, a2, a3, aBase + k16 * 32);
#pragma unroll
            for (int nt = 0; nt < 3; nt++) {
                unsigned int b0, b1;
                ldsm_x2(b0, b1, bBase + nt * 8 * RSTRIDE_B + k16 * 32);
                mma16816(cG[nt], a0, a1, a2, a3, b0, b1);
            }
        }
        {
            int r0 = lane >> 2, c0 = (lane & 3) * 2;
            int bb = mw * 16 + r0;
#pragma unroll
            for (int nt = 0; nt < 3; nt++) {
                Gred[(kw * 32 + bb) * 24 + nt * 8 + c0]         = cG[nt][0];
                Gred[(kw * 32 + bb) * 24 + nt * 8 + c0 + 1]     = cG[nt][1];
                Gred[(kw * 32 + bb + 8) * 24 + nt * 8 + c0]     = cG[nt][2];
                Gred[(kw * 32 + bb + 8) * 24 + nt * 8 + c0 + 1] = cG[nt][3];
            }
        }
        __syncthreads();
        if (tid < 256) {
            float hr = 0.f, hz = 0.f, hn = 0.f;
#pragma unroll
            for (int k = 0; k < 8; k++) {
                int base = (k * 32 + b) * 24;
                hr += Gred[base + jj];
                hz += Gred[base + 8 + jj];
                hn += Gred[base + 16 + jj];
            }
            int row = s * BATCH + b;
            int j = j0 + jj;
            const float* xg = g_enc_xg + (size_t)row * G3;
            float xr = __ldg(xg + j), xz = __ldg(xg + 1024 + j), xn = __ldg(xg + 2048 + j);
            float hprev = g_hbuf[hb][b * HID + j];
            float r = 1.f / (1.f + expf(-(xr + hr + br)));
            float z = 1.f / (1.f + expf(-(xz + hz + bz)));
            float n = tanhf(xn + r * (hn + bn_));
            float hnew = (1.f - z) * n + z * hprev;
            g_hbuf[hb ^ 1][b * HID + j] = hnew;
            __nv_bfloat16 h16 = __float2bfloat16(hnew);
            g_hbuf_bf[hb ^ 1][b * HID + j] = h16;
            g_enc_outs[(size_t)row * HID + j] = hnew;
            g_encouts_bf[(size_t)row * HID + j] = h16;
        }
        grid_sync();
    }
}

// ---------------------------- decoder scan (HMMA) ------------------------
// Weights resident in smem: rows 0..23 Whh(r,z,n), 24..47 Wch(r,z,n), 48..55 W_h.
__global__ void __launch_bounds__(SNTHR) dec_scan(const float* __restrict__ bhh,
                                                  const float* __restrict__ attn_v)
{
    extern __shared__ char sm[];
    __nv_bfloat16* Wsm = (__nv_bfloat16*)sm;
    __nv_bfloat16* hs  = (__nv_bfloat16*)(sm + DEC_HS_OFF);
    float* Gred        = (float*)(sm + DEC_GRED_OFF);
    float* whred       = (float*)(sm + DEC_WHRED_OFF);
    float* s_wh        = (float*)(sm + DEC_SWH_OFF);
    float* s_sc        = (float*)(sm + DEC_SSC_OFF);

    int tid = threadIdx.x;
    int w = tid >> 5, lane = tid & 31;
    int mw = w & 1, kw = w >> 1;
    int j0 = blockIdx.x * 8;

    for (int f = tid; f < 56 * 128; f += SNTHR) {
        int r = f >> 7, c = f & 127;
        const __nv_bfloat16* src;
        if (r < 24) {
            int grow = (r < 8) ? (j0 + r) : (r < 16) ? (1024 + j0 + r - 8) : (2048 + j0 + r - 16);
            src = g_decWhh_bf + (size_t)grow * HID;
        } else if (r < 48) {
            int rr = r - 24;
            int grow = (rr < 8) ? (j0 + rr) : (rr < 16) ? (1024 + j0 + rr - 8) : (2048 + j0 + rr - 16);
            src = g_decWch_bf + (size_t)grow * HID;
        } else {
            src = g_Wh_bf + (size_t)(j0 + r - 48) * HID;
        }
        cp16(smem_u32(Wsm + r * RSTRIDE + c * 8), src + c * 8, true);
    }
    cp_commit(); cp_wait0(); __syncthreads();
    grid_sync();

    int jj = tid & 7, b = tid >> 3;
    float br = 0.f, bz = 0.f, bn_ = 0.f;
    if (tid < 256) {
        br = bhh[j0 + jj]; bz = bhh[1024 + j0 + jj]; bn_ = bhh[2048 + j0 + jj];
    }

    unsigned int aBase = smem_u32(hs) + (unsigned)((mw * 16 + (lane & 15)) * RSTRIDE_B + ((lane >> 4) * 8) * 2);
    unsigned int bBase = smem_u32(Wsm) + (unsigned)((lane & 7) * RSTRIDE_B + (((lane >> 3) & 1) * 8) * 2);

    float hr = 0.f, hz = 0.f, hn = 0.f;   // pass1 results, live across phases (tid<256)

    for (int s = 0; s < SEQ; s++) {
        int hb = s & 1;

        // ---- stage h (bf16)
        for (int f = tid; f < 32 * 128; f += SNTHR) {
            int r = f >> 7, c = f & 127;
            cp16(smem_u32(hs + r * RSTRIDE + c * 8), g_hbuf_bf[hb] + r * HID + c * 8, true);
        }
        cp_commit(); cp_wait0(); __syncthreads();

        // ---- pass1: Whh x h -> cG, W_h x h -> cW
        float cG[3][4], cW[4];
#pragma unroll
        for (int nt = 0; nt < 3; nt++) {
#pragma unroll
            for (int q = 0; q < 4; q++) cG[nt][q] = 0.f;
        }
#pragma unroll
        for (int q = 0; q < 4; q++) cW[q] = 0.f;
#pragma unroll
        for (int kt = 0; kt < 8; kt++) {
            int k16 = kw * 8 + kt;
            unsigned int a0, a1, a2, a3;
            ldsm_x4(a0, a1, a2, a3, aBase + k16 * 32);
#pragma unroll
            for (int nt = 0; nt < 3; nt++) {
                unsigned int b0, b1;
                ldsm_x2(b0, b1, bBase + nt * 8 * RSTRIDE_B + k16 * 32);
                mma16816(cG[nt], a0, a1, a2, a3, b0, b1);
            }
            unsigned int b0, b1;
            ldsm_x2(b0, b1, bBase + 48 * RSTRIDE_B + k16 * 32);
            mma16816(cW, a0, a1, a2, a3, b0, b1);
        }
        {
            int r0 = lane >> 2, c0 = (lane & 3) * 2;
            int bb = mw * 16 + r0;
#pragma unroll
            for (int nt = 0; nt < 3; nt++) {
                Gred[(kw * 32 + bb) * 24 + nt * 8 + c0]         = cG[nt][0];
                Gred[(kw * 32 + bb) * 24 + nt * 8 + c0 + 1]     = cG[nt][1];
                Gred[(kw * 32 + bb + 8) * 24 + nt * 8 + c0]     = cG[nt][2];
                Gred[(kw * 32 + bb + 8) * 24 + nt * 8 + c0 + 1] = cG[nt][3];
            }
            whred[(kw * 32 + bb) * 8 + c0]         = cW[0];
            whred[(kw * 32 + bb) * 8 + c0 + 1]     = cW[1];
            whred[(kw * 32 + bb + 8) * 8 + c0]     = cW[2];
            whred[(kw * 32 + bb + 8) * 8 + c0 + 1] = cW[3];
        }
        __syncthreads();
        if (tid < 256) {
            float whv = 0.f;
            hr = 0.f; hz = 0.f; hn = 0.f;
#pragma unroll
            for (int k = 0; k < 8; k++) {
                int base = k * 32 + b;
                whv += whred[base * 8 + jj];
                hr += Gred[base * 24 + jj];
                hz += Gred[base * 24 + 8 + jj];
                hn += Gred[base * 24 + 16 + jj];
            }
            g_wh[b * HID + j0 + jj] = whv;
        }
        grid_sync();

        // ---- attention: scores -> softmax -> ctx (blocks 0..31, one per batch)
        if (blockIdx.x < BATCH) {
            int bb2 = blockIdx.x;
            for (int k = tid; k < HID; k += SNTHR)
                s_wh[k] = __ldcg(g_wh + bb2 * HID + k);
            __syncthreads();
            for (int sp = w; sp < SEQ; sp += 16) {
                const float* ee = g_enc_energy + (size_t)(sp * BATCH + bb2) * HID;
                float acc = 0.f;
                for (int k = lane; k < HID; k += 32)
                    acc += tanh_approx(__ldg(ee + k) + s_wh[k]) * __ldg(attn_v + k);
#pragma unroll
                for (int o = 16; o; o >>= 1) acc += __shfl_xor_sync(0xffffffffu, acc, o);
                if (lane == 0) s_sc[sp] = acc;
            }
            __syncthreads();
            if (w == 0) {
                float v0 = s_sc[lane], v1 = s_sc[lane + 32];
                float m = fmaxf(v0, v1);
#pragma unroll
                for (int o = 16; o; o >>= 1) m = fmaxf(m, __shfl_xor_sync(0xffffffffu, m, o));
                float e0 = expf(v0 - m), e1 = expf(v1 - m);
                float ssum = e0 + e1;
#pragma unroll
                for (int o = 16; o; o >>= 1) ssum += __shfl_xor_sync(0xffffffffu, ssum, o);
                float inv = 1.f / ssum;
                s_sc[lane] = e0 * inv; s_sc[lane + 32] = e1 * inv;
            }
            __syncthreads();
            for (int jx = tid; jx < HID; jx += SNTHR) {
                float a0 = 0.f, a1 = 0.f, a2 = 0.f, a3 = 0.f;
#pragma unroll 4
                for (int sp = 0; sp < SEQ; sp += 4) {
                    a0 += s_sc[sp]     * __ldg(g_enc_outs + (size_t)((sp)     * BATCH + bb2) * HID + jx);
                    a1 += s_sc[sp + 1] * __ldg(g_enc_outs + (size_t)((sp + 1) * BATCH + bb2) * HID + jx);
                    a2 += s_sc[sp + 2] * __ldg(g_enc_outs + (size_t)((sp + 2) * BATCH + bb2) * HID + jx);
                    a3 += s_sc[sp + 3] * __ldg(g_enc_outs + (size_t)((sp + 3) * BATCH + bb2) * HID + jx);
                }
                g_ctx_bf[bb2 * HID + jx] = __float2bfloat16((a0 + a1) + (a2 + a3));
            }
        }
        grid_sync();

        // ---- stage ctx (bf16), pass2: Wch x ctx -> cC
        for (int f = tid; f < 32 * 128; f += SNTHR) {
            int r = f >> 7, c = f & 127;
            cp16(smem_u32(hs + r * RSTRIDE + c * 8), g_ctx_bf + r * HID + c * 8, true);
        }
        cp_commit(); cp_wait0(); __syncthreads();

        float cC[3][4];
#pragma unroll
        for (int nt = 0; nt < 3; nt++) {
#pragma unroll
            for (int q = 0; q < 4; q++) cC[nt][q] = 0.f;
        }
#pragma unroll
        for (int kt = 0; kt < 8; kt++) {
            int k16 = kw * 8 + kt;
            unsigned int a0, a1, a2, a3;
            ldsm_x4(a0, a1, a2, a3, aBase + k16 * 32);
#pragma unroll
            for (int nt = 0; nt < 3; nt++) {
                unsigned int b0, b1;
                ldsm_x2(b0, b1, bBase + (24 + nt * 8) * RSTRIDE_B + k16 * 32);
                mma16816(cC[nt], a0, a1, a2, a3, b0, b1);
            }
        }
        {
            int r0 = lane >> 2, c0 = (lane & 3) * 2;
            int bb = mw * 16 + r0;
#pragma unroll
            for (int nt = 0; nt < 3; nt++) {
                Gred[(kw * 32 + bb) * 24 + nt * 8 + c0]         = cC[nt][0];
                Gred[(kw * 32 + bb) * 24 + nt * 8 + c0 + 1]     = cC[nt][1];
                Gred[(kw * 32 + bb + 8) * 24 + nt * 8 + c0]     = cC[nt][2];
                Gred[(kw * 32 + bb + 8) * 24 + nt * 8 + c0 + 1] = cC[nt][3];
            }
        }
        __syncthreads();
        if (tid < 256) {
            float cr = 0.f, cz = 0.f, cn = 0.f;
#pragma unroll
            for (int k = 0; k < 8; k++) {
                int base = (k * 32 + b) * 24;
                cr += Gred[base + jj];
                cz += Gred[base + 8 + jj];
                cn += Gred[base + 16 + jj];
            }
            int row = s * BATCH + b;
            int j = j0 + jj;
            const float* xg = g_dec_xg + (size_t)row * G3;
            float xr = __ldg(xg + j) + cr;
            float xz = __ldg(xg + 1024 + j) + cz;
            float xn = __ldg(xg + 2048 + j) + cn;
            float hprev = g_hbuf[hb][b * HID + j];
            float r = 1.f / (1.f + expf(-(xr + hr + br)));
            float z = 1.f / (1.f + expf(-(xz + hz + bz)));
            float n = tanhf(xn + r * (hn + bn_));
            float hnew = (1.f - z) * n + z * hprev;
            g_hbuf[hb ^ 1][b * HID + j] = hnew;
            __nv_bfloat16 h16 = __float2bfloat16(hnew);
            g_hbuf_bf[hb ^ 1][b * HID + j] = h16;
            g_dech_bf[(size_t)row * HID + j] = h16;
        }
        grid_sync();
    }
}

// ------------------------------- loss ------------------------------------
__global__ void __launch_bounds__(256) loss_rows(const int* __restrict__ t,
                                                 const int* __restrict__ tlen)
{
    __shared__ float red[256];
    int row = blockIdx.x;
    int sp = row >> 5, b = row & 31;
    const float* lr = g_logits + (size_t)row * VOC;
    int tid = threadIdx.x;
    float m = -3.4e38f;
    for (int i = tid; i < VOC; i += 256) m = fmaxf(m, lr[i]);
    red[tid] = m; __syncthreads();
    for (int o = 128; o; o >>= 1) {
        if (tid < o) red[tid] = fmaxf(red[tid], red[tid + o]);
        __syncthreads();
    }
    m = red[0]; __syncthreads();
    float ssum = 0.f;
    for (int i = tid; i < VOC; i += 256) ssum += expf(lr[i] - m);
    red[tid] = ssum; __syncthreads();
    for (int o = 128; o; o >>= 1) {
        if (tid < o) red[tid] += red[tid + o];
        __syncthreads();
    }
    if (tid == 0) {
        int tgt = t[b * SEQ + sp];
        float lp = lr[tgt] - m - logf(red[0]);
        g_tok_lp[row] = (sp < tlen[b]) ? lp : 0.f;
    }
}

__global__ void __launch_bounds__(256) loss_final(const int* __restrict__ tlen,
                                                  float* __restrict__ out)
{
    __shared__ float red[256];
    int tid = threadIdx.x;
    float ssum = 0.f;
    for (int r = tid; r < ROWS; r += 256) ssum += g_tok_lp[r];
    red[tid] = ssum; __syncthreads();
    for (int o = 128; o; o >>= 1) {
        if (tid < o) red[tid] += red[tid + o];
        __syncthreads();
    }
    if (tid == 0) {
        float cnt = 0.f;
        for (int b = 0; b < BATCH; b++) cnt += (float)tlen[b];
        out[0] = -red[0] / cnt;
    }
}

// ------------------------------- launch ----------------------------------
extern "C" void kernel_launch(void* const* d_in, const int* in_sizes, int n_in,
                              void* d_out, int out_size)
{
    const int* s         = (const int*)d_in[0];
    const int* t         = (const int*)d_in[1];
    const int* tlen      = (const int*)d_in[2];
    const float* emb     = (const float*)d_in[3];
    const float* enc_Wih = (const float*)d_in[4];
    const float* enc_Whh = (const float*)d_in[5];
    const float* enc_bih = (const float*)d_in[6];
    const float* enc_bhh = (const float*)d_in[7];
    const float* dec_Wih = (const float*)d_in[8];
    const float* dec_Whh = (const float*)d_in[9];
    const float* dec_Wch = (const float*)d_in[10];
    const float* dec_bih = (const float*)d_in[11];
    const float* dec_bhh = (const float*)d_in[12];
    const float* attn_W  = (const float*)d_in[13];
    const float* attn_v  = (const float*)d_in[14];
    const float* Wout    = (const float*)d_in[15];
    const float* bout    = (const float*)d_in[16];
    float* out = (float*)d_out;

    cudaFuncSetAttribute((const void*)enc_scan,
                         cudaFuncAttributeMaxDynamicSharedMemorySize, ENC_SM_TOTAL);
    cudaFuncSetAttribute((const void*)dec_scan,
                         cudaFuncAttributeMaxDynamicSharedMemorySize, DEC_SM_TOTAL);

    build_gather<<<8, 256>>>(s, t);
    f2bf<<<(VOC * EMB / 4 + 255) / 256, 256>>>(emb, VOC * EMB, 0);
    f2bf<<<(G3 * EMB / 4 + 255) / 256, 256>>>(enc_Wih, G3 * EMB, 1);
    f2bf<<<(G3 * EMB / 4 + 255) / 256, 256>>>(dec_Wih, G3 * EMB, 2);
    f2bf<<<(G3 * HID / 4 + 255) / 256, 256>>>(enc_Whh, G3 * HID, 4);
    f2bf<<<(G3 * HID / 4 + 255) / 256, 256>>>(dec_Whh, G3 * HID, 5);
    f2bf<<<(G3 * HID / 4 + 255) / 256, 256>>>(dec_Wch, G3 * HID, 6);
    conv_attnW<<<HID * HID / 256, 256>>>(attn_W);
    f2bf<<<(VOC * HID / 4 + 255) / 256, 256>>>(Wout, VOC * HID, 3);

    hgemm<<<dim3(G3 / 128, ROWS / 128), 256>>>(0, enc_bih);
    hgemm<<<dim3(G3 / 128, ROWS / 128), 256>>>(1, dec_bih);
    enc_scan<<<NBLK, SNTHR, ENC_SM_TOTAL>>>(enc_bhh);
    hgemm<<<dim3(HID / 128, ROWS / 128), 256>>>(2, (const float*)0);
    dec_scan<<<NBLK, SNTHR, DEC_SM_TOTAL>>>(dec_bhh, attn_v);
    hgemm<<<dim3(VOC / 128, ROWS / 128), 256>>>(3, bout);
    loss_rows<<<ROWS, 256>>>(t, tlen);
    loss_final<<<1, 256>>>(tlen, out);
}

// round 8
// speedup vs baseline: 5.7542x; 1.2042x over previous
#include <cuda_runtime.h>
#include <cuda_bf16.h>
#include <cstdint>
#include <cstddef>
#include <math.h>

#define BATCH 32
#define SEQ   64
#define HID   1024
#define EMB   512
#define VOC   32000
#define G3    3072
#define ROWS  2048   // SEQ*BATCH
#define LNB   250    // VOC/128 logits col-blocks

#define NBLK  128    // persistent scan blocks (HID/8)
#define SNTHR 512    // 16 warps

// padded smem row stride for bf16 weight/activation tiles: 1024 + 8 elems
#define RSTRIDE 1032           // elements
#define RSTRIDE_B 2064         // bytes

// enc smem carve
#define ENC_W_BYTES   (24 * RSTRIDE_B)                 // 49536
#define ENC_HS_OFF    ENC_W_BYTES
#define ENC_GRED_OFF  (ENC_HS_OFF + 32 * RSTRIDE_B)    // 115584
#define ENC_SM_TOTAL  (ENC_GRED_OFF + 8 * 32 * 24 * 4) // 140160

// dec smem carve
#define DEC_W_BYTES   (56 * RSTRIDE_B)                  // 115584
#define DEC_HS_OFF    DEC_W_BYTES
#define DEC_GRED_OFF  (DEC_HS_OFF + 32 * RSTRIDE_B)     // 181632
#define DEC_WHRED_OFF (DEC_GRED_OFF + 8 * 32 * 24 * 4)  // 206208
#define DEC_SSC_OFF   (DEC_WHRED_OFF + 8 * 32 * 8 * 4)  // 214400
#define DEC_SM_TOTAL  (DEC_SSC_OFF + SEQ * 4)           // 214656

// ------------------------------ scratch ---------------------------------
__device__ float g_enc_xg[ROWS * G3];
__device__ float g_dec_xg[ROWS * G3];
__device__ float g_enc_outs[ROWS * HID];
__device__ float g_enc_energy[ROWS * HID];
__device__ float g_hbuf[2][BATCH * HID];
__device__ float g_wh[BATCH * HID];
__device__ float g_scores[BATCH * SEQ];
__device__ float g_tok_lp[ROWS];
__device__ float g_tgtlog[ROWS];
__device__ int   g_gidx_enc[ROWS];
__device__ int   g_gidx_dec[ROWS];
__device__ int   g_tgtcol[ROWS];
__device__ __align__(16) float2 g_part[(size_t)ROWS * LNB];
__device__ unsigned g_bar_arrive = 0;
__device__ volatile unsigned g_bar_phase = 0;

// bf16 operands
__device__ __align__(16) __nv_bfloat16 g_emb_bf[VOC * EMB];
__device__ __align__(16) __nv_bfloat16 g_encWih_bf[G3 * EMB];
__device__ __align__(16) __nv_bfloat16 g_decWih_bf[G3 * EMB];
__device__ __align__(16) __nv_bfloat16 g_We_bf[HID * HID];
__device__ __align__(16) __nv_bfloat16 g_Wh_bf[HID * HID];
__device__ __align__(16) __nv_bfloat16 g_Wout_bf[(size_t)VOC * HID];
__device__ __align__(16) __nv_bfloat16 g_encouts_bf[ROWS * HID];
__device__ __align__(16) __nv_bfloat16 g_dech_bf[ROWS * HID];
__device__ __align__(16) __nv_bfloat16 g_encWhh_bf[G3 * HID];
__device__ __align__(16) __nv_bfloat16 g_decWhh_bf[G3 * HID];
__device__ __align__(16) __nv_bfloat16 g_decWch_bf[G3 * HID];
__device__ __align__(16) __nv_bfloat16 g_hbuf_bf[2][BATCH * HID];
__device__ __align__(16) __nv_bfloat16 g_ctx_bf[BATCH * HID];

// ------------------------------ helpers ---------------------------------
__device__ __forceinline__ float tanh_approx(float x) {
    float y; asm("tanh.approx.f32 %0, %1;" : "=f"(y) : "f"(x)); return y;
}

__device__ __forceinline__ void grid_sync() {
    __syncthreads();
    if (threadIdx.x == 0) {
        __threadfence();
        unsigned ph = g_bar_phase;
        unsigned a = atomicAdd(&g_bar_arrive, 1u);
        if (a == (unsigned)(NBLK - 1)) {
            g_bar_arrive = 0u;
            __threadfence();
            g_bar_phase = ph + 1u;
        } else {
            while (g_bar_phase == ph) { __nanosleep(32); }
        }
    }
    __syncthreads();
}

__device__ __forceinline__ unsigned int smem_u32(const void* p) {
    return (unsigned int)__cvta_generic_to_shared(p);
}
__device__ __forceinline__ void cp16(unsigned int dst, const void* src, bool pred) {
    int sz = pred ? 16 : 0;
    asm volatile("cp.async.cg.shared.global [%0], [%1], 16, %2;\n"
                 :: "r"(dst), "l"(src), "r"(sz));
}
__device__ __forceinline__ void cp_commit() { asm volatile("cp.async.commit_group;\n"); }
__device__ __forceinline__ void cp_wait0()  { asm volatile("cp.async.wait_group 0;\n"); }
__device__ __forceinline__ void ldsm_x4(unsigned int& r0, unsigned int& r1,
                                        unsigned int& r2, unsigned int& r3, unsigned int a) {
    asm volatile("ldmatrix.sync.aligned.m8n8.x4.shared.b16 {%0,%1,%2,%3},[%4];"
                 : "=r"(r0), "=r"(r1), "=r"(r2), "=r"(r3) : "r"(a));
}
__device__ __forceinline__ void ldsm_x2(unsigned int& r0, unsigned int& r1, unsigned int a) {
    asm volatile("ldmatrix.sync.aligned.m8n8.x2.shared.b16 {%0,%1},[%2];"
                 : "=r"(r0), "=r"(r1) : "r"(a));
}
__device__ __forceinline__ void mma16816(float* c, unsigned int a0, unsigned int a1,
                                         unsigned int a2, unsigned int a3,
                                         unsigned int b0, unsigned int b1) {
    asm volatile("mma.sync.aligned.m16n8k16.row.col.f32.bf16.bf16.f32 "
                 "{%0,%1,%2,%3},{%4,%5,%6,%7},{%8,%9},{%0,%1,%2,%3};"
                 : "+f"(c[0]), "+f"(c[1]), "+f"(c[2]), "+f"(c[3])
                 : "r"(a0), "r"(a1), "r"(a2), "r"(a3), "r"(b0), "r"(b1));
}

// --------------------------- gather indices -----------------------------
__global__ void build_gather(const int* __restrict__ s, const int* __restrict__ t) {
    int r = blockIdx.x * blockDim.x + threadIdx.x;
    if (r >= ROWS) return;
    int sp = r >> 5, b = r & 31;
    g_gidx_enc[r] = s[b * SEQ + sp];
    g_gidx_dec[r] = (sp == 0) ? -1 : t[b * SEQ + sp - 1];
    g_tgtcol[r] = t[b * SEQ + sp];
}

// ---------------------------- fp32 -> bf16 -------------------------------
// which: 0=emb 1=encWih 2=decWih 3=Wout 4=encWhh 5=decWhh 6=decWch
__global__ void f2bf(const float* __restrict__ src, int n, int which) {
    __nv_bfloat16* d;
    if (which == 0) d = g_emb_bf;
    else if (which == 1) d = g_encWih_bf;
    else if (which == 2) d = g_decWih_bf;
    else if (which == 3) d = g_Wout_bf;
    else if (which == 4) d = g_encWhh_bf;
    else if (which == 5) d = g_decWhh_bf;
    else d = g_decWch_bf;
    int i = (blockIdx.x * blockDim.x + threadIdx.x) * 4;
    if (i < n) {
        float4 v = *(const float4*)(src + i);
        __nv_bfloat16 o[4];
        o[0] = __float2bfloat16(v.x);
        o[1] = __float2bfloat16(v.y);
        o[2] = __float2bfloat16(v.z);
        o[3] = __float2bfloat16(v.w);
        *(uint2*)(d + i) = *(const uint2*)o;
    }
}

__global__ void conv_attnW(const float* __restrict__ attn_W) {
    int i = blockIdx.x * blockDim.x + threadIdx.x;
    if (i < HID * HID) {
        int j = i >> 10;
        int k = i & 1023;
        g_We_bf[i] = __float2bfloat16(attn_W[(size_t)j * 2048 + 1024 + k]);
        g_Wh_bf[i] = __float2bfloat16(attn_W[(size_t)j * 2048 + k]);
    }
}

// ---------------------------- bf16 HMMA GEMM -----------------------------
// which 3 (logits) does NOT write C: fused log-softmax partial epilogue.
#define PADK 40
__global__ void __launch_bounds__(256) hgemm(int which, const float* __restrict__ bias)
{
    __shared__ __nv_bfloat16 As[2][128][PADK];
    __shared__ __nv_bfloat16 Bs[2][128][PADK];
    const unsigned int STG = 128 * PADK * 2;

    const __nv_bfloat16* A;
    const __nv_bfloat16* Wb;
    float* C;
    int N, K, gmode;
    if (which == 0) {
        A = g_emb_bf; Wb = g_encWih_bf; C = g_enc_xg; N = G3; K = EMB; gmode = 1;
    } else if (which == 1) {
        A = g_emb_bf; Wb = g_decWih_bf; C = g_dec_xg; N = G3; K = EMB; gmode = 2;
    } else if (which == 2) {
        A = g_encouts_bf; Wb = g_We_bf; C = g_enc_energy; N = HID; K = HID; gmode = 0;
    } else {
        A = g_dech_bf; Wb = g_Wout_bf; C = (float*)0; N = VOC; K = HID; gmode = 0;
    }

    int tid = threadIdx.x;
    int bn = blockIdx.x, bm = blockIdx.y;
    int warp = tid >> 5, lane = tid & 31;
    int wm = warp >> 2, wn = warp & 3;

    int lr = tid >> 2;
    int lc = (tid & 3) * 8;

    const __nv_bfloat16 *a0, *a1;
    bool p0 = true, p1 = true;
    int gm0 = bm * 128 + lr, gm1 = gm0 + 64;
    if (gmode == 0) {
        a0 = A + (size_t)gm0 * K;
        a1 = A + (size_t)gm1 * K;
    } else {
        const int* gi = (gmode == 1) ? g_gidx_enc : g_gidx_dec;
        int i0 = gi[gm0], i1 = gi[gm1];
        p0 = (i0 >= 0);
        p1 = (i1 >= 0);
        a0 = A + (size_t)(p0 ? i0 : 0) * K;
        a1 = A + (size_t)(p1 ? i1 : 0) * K;
    }
    const __nv_bfloat16* b0p = Wb + (size_t)(bn * 128 + lr) * K;
    const __nv_bfloat16* b1p = Wb + (size_t)(bn * 128 + lr + 64) * K;

    unsigned int sa0 = smem_u32(&As[0][lr][lc]);
    unsigned int sa1 = smem_u32(&As[0][lr + 64][lc]);
    unsigned int sb0 = smem_u32(&Bs[0][lr][lc]);
    unsigned int sb1 = smem_u32(&Bs[0][lr + 64][lc]);

    float acc[4][4][4];
#pragma unroll
    for (int mi = 0; mi < 4; mi++) {
#pragma unroll
        for (int ni = 0; ni < 4; ni++) {
#pragma unroll
            for (int q = 0; q < 4; q++) acc[mi][ni][q] = 0.f;
        }
    }

    int arow = wm * 64 + (lane & 15);
    int acol_off = (lane >> 4) * 8;
    int brow = wn * 32 + (lane & 7);
    int bcol_off = ((lane >> 3) & 1) * 8;

    int KT = K / 32;
    cp16(sa0, a0 + lc, p0);
    cp16(sa1, a1 + lc, p1);
    cp16(sb0, b0p + lc, true);
    cp16(sb1, b1p + lc, true);
    cp_commit();

    int stage = 0;
    for (int kt = 0; kt < KT; kt++) {
        cp_wait0();
        __syncthreads();
        if (kt + 1 < KT) {
            int k = (kt + 1) * 32;
            unsigned int off = (unsigned int)(stage ^ 1) * STG;
            cp16(sa0 + off, a0 + k + lc, p0);
            cp16(sa1 + off, a1 + k + lc, p1);
            cp16(sb0 + off, b0p + k + lc, true);
            cp16(sb1 + off, b1p + k + lc, true);
            cp_commit();
        }
#pragma unroll
        for (int ks = 0; ks < 32; ks += 16) {
            unsigned int af[4][4];
#pragma unroll
            for (int mi = 0; mi < 4; mi++) {
                unsigned int addr = smem_u32(&As[stage][arow + mi * 16][ks + acol_off]);
                ldsm_x4(af[mi][0], af[mi][1], af[mi][2], af[mi][3], addr);
            }
            unsigned int bfr[4][2];
#pragma unroll
            for (int ni = 0; ni < 4; ni++) {
                unsigned int addr = smem_u32(&Bs[stage][brow + ni * 8][ks + bcol_off]);
                ldsm_x2(bfr[ni][0], bfr[ni][1], addr);
            }
#pragma unroll
            for (int mi = 0; mi < 4; mi++) {
#pragma unroll
                for (int ni = 0; ni < 4; ni++) {
                    mma16816(acc[mi][ni], af[mi][0], af[mi][1], af[mi][2], af[mi][3],
                             bfr[ni][0], bfr[ni][1]);
                }
            }
        }
        stage ^= 1;
    }

    int row_base = bm * 128 + wm * 64;
    int col_base = bn * 128 + wn * 32;

    if (which == 3) {
        // fused partial log-softmax epilogue: per-row (max, sumexp) over this
        // block's 128 cols; extract target logit; no C write.
        float* pm = (float*)&As[0][0][0];       // 512 floats
        float* ps = pm + 512;
        float bb2[4][2];
#pragma unroll
        for (int ni = 0; ni < 4; ni++) {
            int c0 = col_base + ni * 8 + (lane & 3) * 2;
            bb2[ni][0] = __ldg(bias + c0);
            bb2[ni][1] = __ldg(bias + c0 + 1);
        }
        __syncthreads();   // As no longer needed by mma
#pragma unroll
        for (int mi = 0; mi < 4; mi++) {
#pragma unroll
            for (int h = 0; h < 2; h++) {
                int rloc = wm * 64 + mi * 16 + (lane >> 2) + 8 * h;
                int grow = bm * 128 + rloc;
                int tc = g_tgtcol[grow] - bn * 128;
                float v[8];
                float m = -3.4e38f;
#pragma unroll
                for (int ni = 0; ni < 4; ni++) {
#pragma unroll
                    for (int q = 0; q < 2; q++) {
                        float x = acc[mi][ni][2 * h + q] + bb2[ni][q];
                        v[ni * 2 + q] = x;
                        m = fmaxf(m, x);
                        int cl = wn * 32 + ni * 8 + (lane & 3) * 2 + q;
                        if (cl == tc) g_tgtlog[grow] = x;
                    }
                }
                float ssum = 0.f;
#pragma unroll
                for (int k2 = 0; k2 < 8; k2++) ssum += __expf(v[k2] - m);
#pragma unroll
                for (int off = 1; off <= 2; off <<= 1) {
                    float mo = __shfl_xor_sync(0xffffffffu, m, off);
                    float so = __shfl_xor_sync(0xffffffffu, ssum, off);
                    float M = fmaxf(m, mo);
                    ssum = ssum * __expf(m - M) + so * __expf(mo - M);
                    m = M;
                }
                if ((lane & 3) == 0) { pm[rloc * 4 + wn] = m; ps[rloc * 4 + wn] = ssum; }
            }
        }
        __syncthreads();
        if (tid < 128) {
            float m = pm[tid * 4], s2 = ps[tid * 4];
#pragma unroll
            for (int w2 = 1; w2 < 4; w2++) {
                float mo = pm[tid * 4 + w2], so = ps[tid * 4 + w2];
                float M = fmaxf(m, mo);
                s2 = s2 * __expf(m - M) + so * __expf(mo - M);
                m = M;
            }
            g_part[(size_t)(bm * 128 + tid) * LNB + bn] = make_float2(m, s2);
        }
        return;
    }

#pragma unroll
    for (int mi = 0; mi < 4; mi++) {
#pragma unroll
        for (int ni = 0; ni < 4; ni++) {
            int r0 = row_base + mi * 16 + (lane >> 2);
            int c0 = col_base + ni * 8 + (lane & 3) * 2;
            float bv0 = bias ? __ldg(bias + c0) : 0.f;
            float bv1 = bias ? __ldg(bias + c0 + 1) : 0.f;
            float2 v0 = make_float2(acc[mi][ni][0] + bv0, acc[mi][ni][1] + bv1);
            float2 v1 = make_float2(acc[mi][ni][2] + bv0, acc[mi][ni][3] + bv1);
            *(float2*)(C + (size_t)r0 * N + c0) = v0;
            *(float2*)(C + (size_t)(r0 + 8) * N + c0) = v1;
        }
    }
}

// ---------------------------- encoder scan (HMMA) ------------------------
__global__ void __launch_bounds__(SNTHR) enc_scan(const float* __restrict__ bhh)
{
    extern __shared__ char sm[];
    __nv_bfloat16* Wsm = (__nv_bfloat16*)sm;
    __nv_bfloat16* hs  = (__nv_bfloat16*)(sm + ENC_HS_OFF);
    float* Gred        = (float*)(sm + ENC_GRED_OFF);

    int tid = threadIdx.x;
    int w = tid >> 5, lane = tid & 31;
    int mw = w & 1, kw = w >> 1;
    int j0 = blockIdx.x * 8;

    for (int f = tid; f < 24 * 128; f += SNTHR) {
        int r = f >> 7, c = f & 127;
        int grow = (r < 8) ? (j0 + r) : (r < 16) ? (1024 + j0 + r - 8) : (2048 + j0 + r - 16);
        cp16(smem_u32(Wsm + r * RSTRIDE + c * 8), g_encWhh_bf + (size_t)grow * HID + c * 8, true);
    }
    cp_commit();
    for (int i = blockIdx.x * SNTHR + tid; i < BATCH * HID; i += NBLK * SNTHR) {
        g_hbuf[0][i] = 0.f;
        g_hbuf_bf[0][i] = __float2bfloat16(0.f);
    }
    cp_wait0();
    __syncthreads();
    grid_sync();

    int jj = tid & 7, b = tid >> 3;
    float br = 0.f, bz = 0.f, bn_ = 0.f;
    if (tid < 256) {
        br = bhh[j0 + jj]; bz = bhh[1024 + j0 + jj]; bn_ = bhh[2048 + j0 + jj];
    }

    unsigned int aBase = smem_u32(hs) + (unsigned)((mw * 16 + (lane & 15)) * RSTRIDE_B + ((lane >> 4) * 8) * 2);
    unsigned int bBase = smem_u32(Wsm) + (unsigned)((lane & 7) * RSTRIDE_B + (((lane >> 3) & 1) * 8) * 2);

    for (int s = 0; s < SEQ; s++) {
        int hb = s & 1;
        for (int f = tid; f < 32 * 128; f += SNTHR) {
            int r = f >> 7, c = f & 127;
            cp16(smem_u32(hs + r * RSTRIDE + c * 8), g_hbuf_bf[hb] + r * HID + c * 8, true);
        }
        cp_commit(); cp_wait0(); __syncthreads();

        float cG[3][4];
#pragma unroll
        for (int nt = 0; nt < 3; nt++) {
#pragma unroll
            for (int q = 0; q < 4; q++) cG[nt][q] = 0.f;
        }
#pragma unroll
        for (int kt = 0; kt < 8; kt++) {
            int k16 = kw * 8 + kt;
            unsigned int a0, a1, a2, a3;
            ldsm_x4(a0, a1, a2, a3, aBase + k16 * 32);
#pragma unroll
            for (int nt = 0; nt < 3; nt++) {
                unsigned int b0, b1;
                ldsm_x2(b0, b1, bBase + nt * 8 * RSTRIDE_B + k16 * 32);
                mma16816(cG[nt], a0, a1, a2, a3, b0, b1);
            }
        }
        {
            int r0 = lane >> 2, c0 = (lane & 3) * 2;
            int bb = mw * 16 + r0;
#pragma unroll
            for (int nt = 0; nt < 3; nt++) {
                Gred[(kw * 32 + bb) * 24 + nt * 8 + c0]         = cG[nt][0];
                Gred[(kw * 32 + bb) * 24 + nt * 8 + c0 + 1]     = cG[nt][1];
                Gred[(kw * 32 + bb + 8) * 24 + nt * 8 + c0]     = cG[nt][2];
                Gred[(kw * 32 + bb + 8) * 24 + nt * 8 + c0 + 1] = cG[nt][3];
            }
        }
        __syncthreads();
        if (tid < 256) {
            float hr = 0.f, hz = 0.f, hn = 0.f;
#pragma unroll
            for (int k = 0; k < 8; k++) {
                int base = (k * 32 + b) * 24;
                hr += Gred[base + jj];
                hz += Gred[base + 8 + jj];
                hn += Gred[base + 16 + jj];
            }
            int row = s * BATCH + b;
            int j = j0 + jj;
            const float* xg = g_enc_xg + (size_t)row * G3;
            float xr = __ldg(xg + j), xz = __ldg(xg + 1024 + j), xn = __ldg(xg + 2048 + j);
            float hprev = g_hbuf[hb][b * HID + j];
            float r = 1.f / (1.f + expf(-(xr + hr + br)));
            float z = 1.f / (1.f + expf(-(xz + hz + bz)));
            float n = tanhf(xn + r * (hn + bn_));
            float hnew = (1.f - z) * n + z * hprev;
            g_hbuf[hb ^ 1][b * HID + j] = hnew;
            __nv_bfloat16 h16 = __float2bfloat16(hnew);
            g_hbuf_bf[hb ^ 1][b * HID + j] = h16;
            g_enc_outs[(size_t)row * HID + j] = hnew;
            g_encouts_bf[(size_t)row * HID + j] = h16;
        }
        grid_sync();
    }
}

// ---------------------------- decoder scan (HMMA) ------------------------
__global__ void __launch_bounds__(SNTHR) dec_scan(const float* __restrict__ bhh,
                                                  const float* __restrict__ attn_v)
{
    extern __shared__ char sm[];
    __nv_bfloat16* Wsm = (__nv_bfloat16*)sm;
    __nv_bfloat16* hs  = (__nv_bfloat16*)(sm + DEC_HS_OFF);
    float* Gred        = (float*)(sm + DEC_GRED_OFF);
    float* whred       = (float*)(sm + DEC_WHRED_OFF);
    float* s_sc        = (float*)(sm + DEC_SSC_OFF);

    int tid = threadIdx.x;
    int w = tid >> 5, lane = tid & 31;
    int mw = w & 1, kw = w >> 1;
    int j0 = blockIdx.x * 8;

    for (int f = tid; f < 56 * 128; f += SNTHR) {
        int r = f >> 7, c = f & 127;
        const __nv_bfloat16* src;
        if (r < 24) {
            int grow = (r < 8) ? (j0 + r) : (r < 16) ? (1024 + j0 + r - 8) : (2048 + j0 + r - 16);
            src = g_decWhh_bf + (size_t)grow * HID;
        } else if (r < 48) {
            int rr = r - 24;
            int grow = (rr < 8) ? (j0 + rr) : (rr < 16) ? (1024 + j0 + rr - 8) : (2048 + j0 + rr - 16);
            src = g_decWch_bf + (size_t)grow * HID;
        } else {
            src = g_Wh_bf + (size_t)(j0 + r - 48) * HID;
        }
        cp16(smem_u32(Wsm + r * RSTRIDE + c * 8), src + c * 8, true);
    }
    cp_commit(); cp_wait0(); __syncthreads();
    grid_sync();

    int jj = tid & 7, b = tid >> 3;
    float br = 0.f, bz = 0.f, bn_ = 0.f;
    if (tid < 256) {
        br = bhh[j0 + jj]; bz = bhh[1024 + j0 + jj]; bn_ = bhh[2048 + j0 + jj];
    }

    unsigned int aBase = smem_u32(hs) + (unsigned)((mw * 16 + (lane & 15)) * RSTRIDE_B + ((lane >> 4) * 8) * 2);
    unsigned int bBase = smem_u32(Wsm) + (unsigned)((lane & 7) * RSTRIDE_B + (((lane >> 3) & 1) * 8) * 2);

    float hr = 0.f, hz = 0.f, hn = 0.f;

    for (int s = 0; s < SEQ; s++) {
        int hb = s & 1;

        // ---- stage h (bf16)
        for (int f = tid; f < 32 * 128; f += SNTHR) {
            int r = f >> 7, c = f & 127;
            cp16(smem_u32(hs + r * RSTRIDE + c * 8), g_hbuf_bf[hb] + r * HID + c * 8, true);
        }
        cp_commit(); cp_wait0(); __syncthreads();

        // ---- pass1: Whh x h -> cG, W_h x h -> cW
        float cG[3][4], cW[4];
#pragma unroll
        for (int nt = 0; nt < 3; nt++) {
#pragma unroll
            for (int q = 0; q < 4; q++) cG[nt][q] = 0.f;
        }
#pragma unroll
        for (int q = 0; q < 4; q++) cW[q] = 0.f;
#pragma unroll
        for (int kt = 0; kt < 8; kt++) {
            int k16 = kw * 8 + kt;
            unsigned int a0, a1, a2, a3;
            ldsm_x4(a0, a1, a2, a3, aBase + k16 * 32);
#pragma unroll
            for (int nt = 0; nt < 3; nt++) {
                unsigned int b0, b1;
                ldsm_x2(b0, b1, bBase + nt * 8 * RSTRIDE_B + k16 * 32);
                mma16816(cG[nt], a0, a1, a2, a3, b0, b1);
            }
            unsigned int b0, b1;
            ldsm_x2(b0, b1, bBase + 48 * RSTRIDE_B + k16 * 32);
            mma16816(cW, a0, a1, a2, a3, b0, b1);
        }
        {
            int r0 = lane >> 2, c0 = (lane & 3) * 2;
            int bb = mw * 16 + r0;
#pragma unroll
            for (int nt = 0; nt < 3; nt++) {
                Gred[(kw * 32 + bb) * 24 + nt * 8 + c0]         = cG[nt][0];
                Gred[(kw * 32 + bb) * 24 + nt * 8 + c0 + 1]     = cG[nt][1];
                Gred[(kw * 32 + bb + 8) * 24 + nt * 8 + c0]     = cG[nt][2];
                Gred[(kw * 32 + bb + 8) * 24 + nt * 8 + c0 + 1] = cG[nt][3];
            }
            whred[(kw * 32 + bb) * 8 + c0]         = cW[0];
            whred[(kw * 32 + bb) * 8 + c0 + 1]     = cW[1];
            whred[(kw * 32 + bb + 8) * 8 + c0]     = cW[2];
            whred[(kw * 32 + bb + 8) * 8 + c0 + 1] = cW[3];
        }
        __syncthreads();
        if (tid < 256) {
            float whv = 0.f;
            hr = 0.f; hz = 0.f; hn = 0.f;
#pragma unroll
            for (int k = 0; k < 8; k++) {
                int base = k * 32 + b;
                whv += whred[base * 8 + jj];
                hr += Gred[base * 24 + jj];
                hz += Gred[base * 24 + 8 + jj];
                hn += Gred[base * 24 + 16 + jj];
            }
            g_wh[b * HID + j0 + jj] = whv;
        }
        grid_sync();

        // ---- scores: warp-per-(b,sp) across ALL 128 blocks
        {
            int b2 = blockIdx.x & 31;
            int sp = (blockIdx.x >> 5) * 16 + w;
            const float* ee = g_enc_energy + (size_t)(sp * BATCH + b2) * HID;
            const float* whp = g_wh + b2 * HID;
            float acc = 0.f;
            for (int k = lane; k < HID; k += 32)
                acc += tanh_approx(__ldg(ee + k) + __ldcg(whp + k)) * __ldg(attn_v + k);
#pragma unroll
            for (int o = 16; o; o >>= 1) acc += __shfl_xor_sync(0xffffffffu, acc, o);
            if (lane == 0) g_scores[b2 * SEQ + sp] = acc;
        }
        grid_sync();

        // ---- softmax + ctx: block = (b, j-quarter)
        {
            int b2 = blockIdx.x & 31;
            int jq = blockIdx.x >> 5;
            if (tid < SEQ) s_sc[tid] = __ldcg(g_scores + b2 * SEQ + tid);
            __syncthreads();
            if (w == 0) {
                float v0 = s_sc[lane], v1 = s_sc[lane + 32];
                float m = fmaxf(v0, v1);
#pragma unroll
                for (int o = 16; o; o >>= 1) m = fmaxf(m, __shfl_xor_sync(0xffffffffu, m, o));
                float e0 = expf(v0 - m), e1 = expf(v1 - m);
                float ssum = e0 + e1;
#pragma unroll
                for (int o = 16; o; o >>= 1) ssum += __shfl_xor_sync(0xffffffffu, ssum, o);
                float inv = 1.f / ssum;
                s_sc[lane] = e0 * inv; s_sc[lane + 32] = e1 * inv;
            }
            __syncthreads();
            if (tid < 256) {
                int jx = jq * 256 + tid;
                float a0 = 0.f, a1 = 0.f, a2 = 0.f, a3 = 0.f;
#pragma unroll 4
                for (int sp = 0; sp < SEQ; sp += 4) {
                    a0 += s_sc[sp]     * __ldg(g_enc_outs + (size_t)((sp)     * BATCH + b2) * HID + jx);
                    a1 += s_sc[sp + 1] * __ldg(g_enc_outs + (size_t)((sp + 1) * BATCH + b2) * HID + jx);
                    a2 += s_sc[sp + 2] * __ldg(g_enc_outs + (size_t)((sp + 2) * BATCH + b2) * HID + jx);
                    a3 += s_sc[sp + 3] * __ldg(g_enc_outs + (size_t)((sp + 3) * BATCH + b2) * HID + jx);
                }
                g_ctx_bf[b2 * HID + jx] = __float2bfloat16((a0 + a1) + (a2 + a3));
            }
        }
        grid_sync();

        // ---- stage ctx (bf16), pass2: Wch x ctx -> cC
        for (int f = tid; f < 32 * 128; f += SNTHR) {
            int r = f >> 7, c = f & 127;
            cp16(smem_u32(hs + r * RSTRIDE + c * 8), g_ctx_bf + r * HID + c * 8, true);
        }
        cp_commit(); cp_wait0(); __syncthreads();

        float cC[3][4];
#pragma unroll
        for (int nt = 0; nt < 3; nt++) {
#pragma unroll
            for (int q = 0; q < 4; q++) cC[nt][q] = 0.f;
        }
#pragma unroll
        for (int kt = 0; kt < 8; kt++) {
            int k16 = kw * 8 + kt;
            unsigned int a0, a1, a2, a3;
            ldsm_x4(a0, a1, a2, a3, aBase + k16 * 32);
#pragma unroll
            for (int nt = 0; nt < 3; nt++) {
                unsigned int b0, b1;
                ldsm_x2(b0, b1, bBase + (24 + nt * 8) * RSTRIDE_B + k16 * 32);
                mma16816(cC[nt], a0, a1, a2, a3, b0, b1);
            }
        }
        {
            int r0 = lane >> 2, c0 = (lane & 3) * 2;
            int bb = mw * 16 + r0;
#pragma unroll
            for (int nt = 0; nt < 3; nt++) {
                Gred[(kw * 32 + bb) * 24 + nt * 8 + c0]         = cC[nt][0];
                Gred[(kw * 32 + bb) * 24 + nt * 8 + c0 + 1]     = cC[nt][1];
                Gred[(kw * 32 + bb + 8) * 24 + nt * 8 + c0]     = cC[nt][2];
                Gred[(kw * 32 + bb + 8) * 24 + nt * 8 + c0 + 1] = cC[nt][3];
            }
        }
        __syncthreads();
        if (tid < 256) {
            float cr = 0.f, cz = 0.f, cn = 0.f;
#pragma unroll
            for (int k = 0; k < 8; k++) {
                int base = (k * 32 + b) * 24;
                cr += Gred[base + jj];
                cz += Gred[base + 8 + jj];
                cn += Gred[base + 16 + jj];
            }
            int row = s * BATCH + b;
            int j = j0 + jj;
            const float* xg = g_dec_xg + (size_t)row * G3;
            float xr = __ldg(xg + j) + cr;
            float xz = __ldg(xg + 1024 + j) + cz;
            float xn = __ldg(xg + 2048 + j) + cn;
            float hprev = g_hbuf[hb][b * HID + j];
            float r = 1.f / (1.f + expf(-(xr + hr + br)));
            float z = 1.f / (1.f + expf(-(xz + hz + bz)));
            float n = tanhf(xn + r * (hn + bn_));
            float hnew = (1.f - z) * n + z * hprev;
            g_hbuf[hb ^ 1][b * HID + j] = hnew;
            __nv_bfloat16 h16 = __float2bfloat16(hnew);
            g_hbuf_bf[hb ^ 1][b * HID + j] = h16;
            g_dech_bf[(size_t)row * HID + j] = h16;
        }
        grid_sync();
    }
}

// ------------------------------- loss ------------------------------------
// combine 250 (max,sumexp) partials per row; warp per row.
__global__ void __launch_bounds__(256) loss_combine(const int* __restrict__ tlen)
{
    int w = threadIdx.x >> 5, lane = threadIdx.x & 31;
    int row = blockIdx.x * 8 + w;
    float m = -3.4e38f, s = 0.f;
    for (int i = lane; i < LNB; i += 32) {
        float2 p = g_part[(size_t)row * LNB + i];
        float M = fmaxf(m, p.x);
        s = s * __expf(m - M) + p.y * __expf(p.x - M);
        m = M;
    }
#pragma unroll
    for (int o = 16; o; o >>= 1) {
        float mo = __shfl_xor_sync(0xffffffffu, m, o);
        float so = __shfl_xor_sync(0xffffffffu, s, o);
        float M = fmaxf(m, mo);
        s = s * __expf(m - M) + so * __expf(mo - M);
        m = M;
    }
    if (lane == 0) {
        int sp = row >> 5, b = row & 31;
        float lp = g_tgtlog[row] - m - logf(s);
        g_tok_lp[row] = (sp < tlen[b]) ? lp : 0.f;
    }
}

__global__ void __launch_bounds__(256) loss_final(const int* __restrict__ tlen,
                                                  float* __restrict__ out)
{
    __shared__ float red[256];
    int tid = threadIdx.x;
    float ssum = 0.f;
    for (int r = tid; r < ROWS; r += 256) ssum += g_tok_lp[r];
    red[tid] = ssum; __syncthreads();
    for (int o = 128; o; o >>= 1) {
        if (tid < o) red[tid] += red[tid + o];
        __syncthreads();
    }
    if (tid == 0) {
        float cnt = 0.f;
        for (int b = 0; b < BATCH; b++) cnt += (float)tlen[b];
        out[0] = -red[0] / cnt;
    }
}

// ------------------------------- launch ----------------------------------
extern "C" void kernel_launch(void* const* d_in, const int* in_sizes, int n_in,
                              void* d_out, int out_size)
{
    const int* s         = (const int*)d_in[0];
    const int* t         = (const int*)d_in[1];
    const int* tlen      = (const int*)d_in[2];
    const float* emb     = (const float*)d_in[3];
    const float* enc_Wih = (const float*)d_in[4];
    const float* enc_Whh = (const float*)d_in[5];
    const float* enc_bih = (const float*)d_in[6];
    const float* enc_bhh = (const float*)d_in[7];
    const float* dec_Wih = (const float*)d_in[8];
    const float* dec_Whh = (const float*)d_in[9];
    const float* dec_Wch = (const float*)d_in[10];
    const float* dec_bih = (const float*)d_in[11];
    const float* dec_bhh = (const float*)d_in[12];
    const float* attn_W  = (const float*)d_in[13];
    const float* attn_v  = (const float*)d_in[14];
    const float* Wout    = (const float*)d_in[15];
    const float* bout    = (const float*)d_in[16];
    float* out = (float*)d_out;

    cudaFuncSetAttribute((const void*)enc_scan,
                         cudaFuncAttributeMaxDynamicSharedMemorySize, ENC_SM_TOTAL);
    cudaFuncSetAttribute((const void*)dec_scan,
                         cudaFuncAttributeMaxDynamicSharedMemorySize, DEC_SM_TOTAL);

    build_gather<<<8, 256>>>(s, t);
    f2bf<<<(VOC * EMB / 4 + 255) / 256, 256>>>(emb, VOC * EMB, 0);
    f2bf<<<(G3 * EMB / 4 + 255) / 256, 256>>>(enc_Wih, G3 * EMB, 1);
    f2bf<<<(G3 * EMB / 4 + 255) / 256, 256>>>(dec_Wih, G3 * EMB, 2);
    f2bf<<<(G3 * HID / 4 + 255) / 256, 256>>>(enc_Whh, G3 * HID, 4);
    f2bf<<<(G3 * HID / 4 + 255) / 256, 256>>>(dec_Whh, G3 * HID, 5);
    f2bf<<<(G3 * HID / 4 + 255) / 256, 256>>>(dec_Wch, G3 * HID, 6);
    conv_attnW<<<HID * HID / 256, 256>>>(attn_W);
    f2bf<<<(VOC * HID / 4 + 255) / 256, 256>>>(Wout, VOC * HID, 3);

    hgemm<<<dim3(G3 / 128, ROWS / 128), 256>>>(0, enc_bih);
    hgemm<<<dim3(G3 / 128, ROWS / 128), 256>>>(1, dec_bih);
    enc_scan<<<NBLK, SNTHR, ENC_SM_TOTAL>>>(enc_bhh);
    hgemm<<<dim3(HID / 128, ROWS / 128), 256>>>(2, (const float*)0);
    dec_scan<<<NBLK, SNTHR, DEC_SM_TOTAL>>>(dec_bhh, attn_v);
    hgemm<<<dim3(VOC / 128, ROWS / 128), 256>>>(3, bout);
    loss_combine<<<ROWS / 8, 256>>>(tlen);
    loss_final<<<1, 256>>>(tlen, out);
}